// round 15
// baseline (speedup 1.0000x reference)
#include <cuda_runtime.h>
#include <math.h>

#define NN 63
#define NP (NN*NN)          // 3969
#define BATCH 256
#define KS 7
#define ML 3
#define CT_SMEM_FLOATS 21504   // 21248 used + 256 pad for tail-quad smem overreads

// ---------------- device scratch ----------------
__device__ float g_cosT[63*68];   // [k][n] rows padded to 68, cols 63..67 = 0
__device__ float g_sinT[63*68];
__device__ float g_cosTT[63*36];  // transposed [n][k2<32], stride 36
__device__ float g_sinTT[63*36];
__device__ float g_w1[BATCH*147];
__device__ float g_w2[BATCH*147];
__device__ float g_a4[BATCH*1089*32];   // [b][pix][ch]
__device__ float g_blocksum[BATCH];

__device__ __forceinline__ float gelu_exact(float v) {
    return v * 0.5f * (1.0f + erff(v * 0.70710678118654752f));
}

__global__ void init_tw_kernel() {
    int idx = blockIdx.x * blockDim.x + threadIdx.x;
    if (idx < 63*68) {
        int k = idx / 68, n = idx % 68;
        if (n < 63) {
            float ang = 6.28318530717958647692f * (float)((k * n) % NN) / 63.0f;
            g_cosT[idx] = cosf(ang);
            g_sinT[idx] = sinf(ang);
        } else { g_cosT[idx] = 0.f; g_sinT[idx] = 0.f; }
    }
    if (idx < 63*36) {
        int n = idx / 36, k2 = idx % 36;
        if (k2 < 32) {
            float ang = 6.28318530717958647692f * (float)((k2 * n) % NN) / 63.0f;
            g_cosTT[idx] = cosf(ang);
            g_sinTT[idx] = sinf(ang);
        } else { g_cosTT[idx] = 0.f; g_sinTT[idx] = 0.f; }
    }
}

// ---------------- hypernet ----------------
__global__ void hyper_kernel(const float* __restrict__ kA,
                             const float* __restrict__ w1a, const float* __restrict__ b1a,
                             const float* __restrict__ w2a, const float* __restrict__ b2a,
                             const float* __restrict__ w1b, const float* __restrict__ b1b,
                             const float* __restrict__ w2b, const float* __restrict__ b2b) {
    int b = blockIdx.x;
    __shared__ float a[9], h1[100], h2[100];
    int t = threadIdx.x;
    if (t < 9) a[t] = kA[b*9 + t];
    __syncthreads();
    if (t < 100) {
        float s = b1a[t];
        #pragma unroll
        for (int i = 0; i < 9; i++) s += a[i] * w1a[i*100 + t];
        h1[t] = gelu_exact(s);
    } else if (t < 200) {
        int h = t - 100;
        float s = b1b[h];
        #pragma unroll
        for (int i = 0; i < 9; i++) s += a[i] * w1b[i*100 + h];
        h2[h] = gelu_exact(s);
    }
    __syncthreads();
    for (int o = t; o < 147; o += blockDim.x) {
        float s1 = b2a[o], s2 = b2b[o];
        for (int h = 0; h < 100; h++) {
            s1 += h1[h] * w2a[h*147 + o];
            s2 += h2[h] * w2b[h*147 + o];
        }
        g_w1[b*147 + o] = s1;
        g_w2[b*147 + o] = s2;
    }
}

// ---------------- fused ConvTranspose chain ct1..ct4 ----------------
__device__ __forceinline__ void load_ctw(const float* __restrict__ w,
                                         const float* __restrict__ bias,
                                         float* s_w, float* s_bias, int tid) {
    for (int idx = tid; idx < 9216; idx += 512) {
        int i = idx & 31, o = (idx >> 5) & 31, k = idx >> 10;
        s_w[k*1040 + (o>>3)*260 + (o&7)*32 + i] = w[(i*32 + o)*9 + k];
    }
    if (tid < 32) s_bias[tid] = bias[tid];
}

__device__ __forceinline__ void ct_store(float* __restrict__ ob, const float* acc) {
    float4 o0 = {gelu_exact(acc[0]), gelu_exact(acc[1]), gelu_exact(acc[2]), gelu_exact(acc[3])};
    float4 o1 = {gelu_exact(acc[4]), gelu_exact(acc[5]), gelu_exact(acc[6]), gelu_exact(acc[7])};
    *(float4*)ob = o0;
    *(float4*)(ob + 4) = o1;
}

// PIXEL-QUAD blocking: each thread computes (y, x+2j), j=0..3 (same parity class
// -> identical tap list & weight addresses -> weight loads amortized over 4
// outputs). Tail-quad over-reads stay inside the padded smem allocation
// (CT_SMEM_FLOATS includes the worst-case 2684-float reach past B2); stores
// predicated per-pixel.
template<int IN_H>
__device__ void ct_midstage(const float* __restrict__ s_in, const float* __restrict__ s_w,
                            const float* __restrict__ s_bias, float* __restrict__ out, int tid) {
    constexpr int OUT_H = 2*IN_H - 1;
    constexpr int EC = (OUT_H + 1) / 2;       // even-column count
    constexpr int OC = OUT_H - EC;            // odd-column count
    constexpr int QE = (EC + 3) / 4;          // even-series quads
    constexpr int QO = (OC + 3) / 4;          // odd-series quads
    constexpr int QPR = QE + QO;              // quads per row
    constexpr int ITEMS = OUT_H * QPR * 4;
    const float4* in4 = (const float4*)s_in;
    const float4* w4  = (const float4*)s_w;
    for (int it = tid; it < ITEMS; it += 512) {
        int og = it & 3, t = it >> 2;
        int y = t / QPR, qr = t % QPR;
        int x;
        if (qr < QE) x = 8*qr;
        else         x = 1 + 8*(qr - QE);
        float acc[4][8];
        #pragma unroll
        for (int j = 0; j < 4; j++)
            #pragma unroll
            for (int ol = 0; ol < 8; ol++) acc[j][ol] = s_bias[og*8 + ol];
        int kys[2], iys[2], nky, kxs[2], ixs[2], nkx;
        if (y & 1) { nky=2; kys[0]=0; iys[0]=(y+1)>>1; kys[1]=2; iys[1]=(y-1)>>1; }
        else       { nky=1; kys[0]=1; iys[0]=y>>1; }
        if (x & 1) { nkx=2; kxs[0]=0; ixs[0]=(x+1)>>1; kxs[1]=2; ixs[1]=(x-1)>>1; }
        else       { nkx=1; kxs[0]=1; ixs[0]=x>>1; }
        for (int p = 0; p < nky; p++)
            for (int q = 0; q < nkx; q++) {
                int base4 = (iys[p]*IN_H + ixs[q]) * 8;
                const float4* wrow = w4 + (kys[p]*3 + kxs[q])*260 + og*65;
                #pragma unroll
                for (int c4 = 0; c4 < 8; c4++) {
                    float4 v0 = in4[base4 + c4];
                    float4 v1 = in4[base4 + 8 + c4];
                    float4 v2 = in4[base4 + 16 + c4];
                    float4 v3 = in4[base4 + 24 + c4];
                    #pragma unroll
                    for (int ol = 0; ol < 8; ol++) {
                        float4 wv = wrow[ol*8 + c4];
                        acc[0][ol] += v0.x*wv.x + v0.y*wv.y + v0.z*wv.z + v0.w*wv.w;
                        acc[1][ol] += v1.x*wv.x + v1.y*wv.y + v1.z*wv.z + v1.w*wv.w;
                        acc[2][ol] += v2.x*wv.x + v2.y*wv.y + v2.z*wv.z + v2.w*wv.w;
                        acc[3][ol] += v3.x*wv.x + v3.y*wv.y + v3.z*wv.z + v3.w*wv.w;
                    }
                }
            }
        int pixA = y*OUT_H + x;
        #pragma unroll
        for (int j = 0; j < 4; j++) {
            if (x + 2*j < OUT_H)
                ct_store(out + (pixA + 2*j)*32 + og*8, acc[j]);
        }
    }
}

__global__ void __launch_bounds__(512) ctchain_kernel(
    const float* __restrict__ kA,
    const float* __restrict__ w1c, const float* __restrict__ b1c,
    const float* __restrict__ w2c, const float* __restrict__ b2c,
    const float* __restrict__ w3c, const float* __restrict__ b3c,
    const float* __restrict__ w4c, const float* __restrict__ b4c) {
    extern __shared__ float cs[];
    float* s_w    = cs;               // 9360
    float* B1     = cs + 9360;        // 9248
    float* B2     = B1 + 9248;        // 2592
    float* s_a    = B2 + 2592;        // 16
    float* s_bias = s_a + 16;         // 32  (then 256-float pad to CT_SMEM_FLOATS)
    int b = blockIdx.x, tid = threadIdx.x;

    if (tid < 9) s_a[tid] = kA[b*9 + tid];
    load_ctw(w2c, b2c, s_w, s_bias, tid);
    __syncthreads();

    for (int el = tid; el < 800; el += 512) {
        int pix = el >> 5, o = el & 31;
        int y = pix / 5, x = pix % 5;
        float acc = b1c[o];
        int kys[2], iys[2], nky, kxs[2], ixs[2], nkx;
        if (y & 1) { nky=2; kys[0]=0; iys[0]=(y+1)>>1; kys[1]=2; iys[1]=(y-1)>>1; }
        else       { nky=1; kys[0]=1; iys[0]=y>>1; }
        if (x & 1) { nkx=2; kxs[0]=0; ixs[0]=(x+1)>>1; kxs[1]=2; ixs[1]=(x-1)>>1; }
        else       { nkx=1; kxs[0]=1; ixs[0]=x>>1; }
        for (int p = 0; p < nky; p++)
            for (int q = 0; q < nkx; q++)
                acc += s_a[iys[p]*3 + ixs[q]] * w1c[o*9 + kys[p]*3 + kxs[q]];
        B1[pix*32 + o] = gelu_exact(acc);
    }
    __syncthreads();

    ct_midstage<5>(B1, s_w, s_bias, B2, tid);
    __syncthreads();
    load_ctw(w3c, b3c, s_w, s_bias, tid);
    __syncthreads();
    ct_midstage<9>(B2, s_w, s_bias, B1, tid);
    __syncthreads();
    load_ctw(w4c, b4c, s_w, s_bias, tid);
    __syncthreads();
    ct_midstage<17>(B1, s_w, s_bias, g_a4 + (size_t)b*1089*32, tid);
}

// ---------------- persistent per-sample solver (R8/R12 verbatim) ----------------
#define O_SXP 0                      // 65x68 = 4420
#define O_SRP 4420                   // 69x72 = 4968
#define O_T   9388                   // 3*4968 = 14904 (ct5 staging 7938 fits)
#define O_PR  24292                  // [m][36] = 2268
#define O_PI  26560
#define O_CR  28828                  // [k1][36] = 2268
#define O_CI  31096
#define O_DR  33364                  // [m][36] = 2268
#define O_DI  35632
#define O_WCR 37900                  // [k1][36] = 2268
#define O_WCI 40168
#define O_CT  42436                  // [k][68] = 4284
#define O_ST  46720
#define O_TTC 51004                  // [n][36] = 2268
#define O_TTS 53272
#define O_W5  55540                  // 576
#define O_W1  56116                  // 160
#define O_W2  56276
#define O_KA  56436
#define SMEM_FLOATS 56452            // 225808 B

__global__ void __launch_bounds__(512) solver_kernel(const float* __restrict__ x_in,
                              const float* __restrict__ f_in,
                              const float* __restrict__ kA,
                              const float* __restrict__ w5, const float* __restrict__ b5) {
    extern __shared__ float sm[];
    float* sxp  = sm + O_SXP;
    float* srp  = sm + O_SRP;
    float* sT   = sm + O_T;
    float* sPr  = sm + O_PR;
    float* sPi  = sm + O_PI;
    float* sCr  = sm + O_CR;
    float* sCi  = sm + O_CI;
    float* sDr  = sm + O_DR;
    float* sDi  = sm + O_DI;
    float* swcr = sm + O_WCR;
    float* swci = sm + O_WCI;
    float* sct  = sm + O_CT;
    float* sst  = sm + O_ST;
    float* sttc = sm + O_TTC;
    float* stts = sm + O_TTS;
    float* sw5  = sm + O_W5;
    float* sw1  = sm + O_W1;
    float* sw2  = sm + O_W2;
    float* ska  = sm + O_KA;

    int b = blockIdx.x, tid = threadIdx.x;
    const int T = 512;
    const float inv = 0.12598815766974242f;  // 1/sqrt(63)

    // ---- init ----
    float fr[8];
    #pragma unroll
    for (int p = 0; p < 8; p++) {
        int el = tid + p*T;
        fr[p] = 0.f;
        if (el < 4032) {
            int i = el >> 6, j = el & 63;
            if (j < 63) {
                fr[p] = f_in[b*NP + i*NN + j];
                sxp[(i+1)*68 + (j+1)] = x_in[b*NP + i*NN + j];
            }
        }
    }
    for (int el = tid; el < 63*68; el += T) { sct[el] = g_cosT[el]; sst[el] = g_sinT[el]; }
    for (int el = tid; el < 63*36; el += T) { sttc[el] = g_cosTT[el]; stts[el] = g_sinTT[el]; }
    for (int c = tid; c < 65; c += T) {
        sxp[c] = (c == 64) ? 1.f : 0.f;
        sxp[64*68 + c] = 1.f;
    }
    for (int r = tid; r < 65; r += T) {
        sxp[r*68] = (r == 64) ? 1.f : 0.f;
        sxp[r*68 + 64] = 1.f;
    }
    for (int idx = tid; idx < 576; idx += T) {
        int k = idx / 64, r = idx & 63, o = r >> 5, i = r & 31;
        sw5[idx] = w5[i*18 + o*9 + k];
    }
    if (tid < 9) ska[tid] = kA[b*9 + tid];
    for (int el = tid; el < 147; el += T) {
        sw1[el] = g_w1[b*147 + el];
        sw2[el] = g_w2[b*147 + el];
    }
    __syncthreads();

    // ---- ct5 fused: h flat [2][63*63] into sT staging ----
    {
        float b0 = b5[0], b1 = b5[1];
        const float4* s_w4 = (const float4*)sw5;
        const float4* gin = (const float4*)(g_a4 + (size_t)b * 1089 * 32);
        for (int pix = tid; pix < NP; pix += T) {
            int y = pix / NN, x = pix % NN;
            float acc0 = b0, acc1 = b1;
            int kys[2], iys[2], nky, kxs[2], ixs[2], nkx;
            if (y & 1) { nky=1; kys[0]=1; iys[0]=(y+1)>>1; }
            else       { nky=2; kys[0]=0; iys[0]=(y+2)>>1; kys[1]=2; iys[1]=y>>1; }
            if (x & 1) { nkx=1; kxs[0]=1; ixs[0]=(x+1)>>1; }
            else       { nkx=2; kxs[0]=0; ixs[0]=(x+2)>>1; kxs[1]=2; ixs[1]=x>>1; }
            for (int p = 0; p < nky; p++)
                for (int q = 0; q < nkx; q++) {
                    int base4 = (iys[p]*33 + ixs[q]) * 8;
                    int kk = kys[p]*3 + kxs[q];
                    #pragma unroll
                    for (int c4 = 0; c4 < 8; c4++) {
                        float4 v = __ldg(gin + base4 + c4);
                        float4 w0 = s_w4[kk*16 + c4];
                        float4 w1 = s_w4[kk*16 + 8 + c4];
                        acc0 += v.x*w0.x + v.y*w0.y + v.z*w0.z + v.w*w0.w;
                        acc1 += v.x*w1.x + v.y*w1.y + v.z*w1.z + v.w*w1.w;
                    }
                }
            sT[pix] = acc0;
            sT[NP + pix] = acc1;
        }
    }
    __syncthreads();
    for (int el = tid; el < 2016; el += T) {
        int k1 = el >> 5, k2 = el & 31;
        int p = k1*63 + k2;
        swcr[k1*36 + k2] = sT[2*p];
        swci[k1*36 + k2] = sT[2*p + 1];
    }
    __syncthreads();
    for (int el = tid; el < 14904; el += T) sT[el] = 0.f;
    for (int el = tid; el < 4968; el += T) srp[el] = 0.f;
    __syncthreads();

    for (int iter = 0; iter < 5; iter++) {
        // ---- (a) residual -> srp ----
        #pragma unroll
        for (int p = 0; p < 8; p++) {
            int el = tid + p*T;
            if (el >= 4032) break;
            int i = el >> 6, j = el & 63;
            if (j >= 63) continue;
            const float* xb = sxp + i*68 + j;
            float acc = ska[0]*xb[0] + ska[1]*xb[1] + ska[2]*xb[2]
                      + ska[3]*xb[68] + ska[4]*xb[69] + ska[5]*xb[70]
                      + ska[6]*xb[136] + ska[7]*xb[137] + ska[8]*xb[138];
            srp[(i+3)*72 + j + 4] = fr[p] - acc;
        }
        __syncthreads();

        // ---- (b) stage1: t[c] = conv7(r, w1[c]) — 2-row blocked, 3 channels ----
        {
            int rpair = tid >> 4, g = tid & 15;
            int i0 = rpair << 1;
            bool two = (i0 + 1 < 63);
            int j0 = g << 2;
            float4 a00={0,0,0,0}, a01={0,0,0,0}, a02={0,0,0,0};
            float4 a10={0,0,0,0}, a11={0,0,0,0}, a12={0,0,0,0};
            #pragma unroll
            for (int rr_ = 0; rr_ < 8; rr_++) {
                if (rr_ == 7 && !two) break;
                const float4* rp4 = (const float4*)(srp + (i0+rr_)*72 + j0);
                float4 Ra = rp4[0], Rb = rp4[1], Rc = rp4[2];
                float rr[12] = {Ra.x,Ra.y,Ra.z,Ra.w, Rb.x,Rb.y,Rb.z,Rb.w, Rc.x,Rc.y,Rc.z,Rc.w};
                if (rr_ < 7) {
                    #pragma unroll
                    for (int v = 0; v < 7; v++) {
                        float w0 = sw1[rr_*7 + v];
                        float w1 = sw1[49 + rr_*7 + v];
                        float w2 = sw1[98 + rr_*7 + v];
                        a00.x += rr[v+1]*w0; a00.y += rr[v+2]*w0; a00.z += rr[v+3]*w0; a00.w += rr[v+4]*w0;
                        a01.x += rr[v+1]*w1; a01.y += rr[v+2]*w1; a01.z += rr[v+3]*w1; a01.w += rr[v+4]*w1;
                        a02.x += rr[v+1]*w2; a02.y += rr[v+2]*w2; a02.z += rr[v+3]*w2; a02.w += rr[v+4]*w2;
                    }
                }
                if (rr_ >= 1) {
                    int u = rr_ - 1;
                    #pragma unroll
                    for (int v = 0; v < 7; v++) {
                        float w0 = sw1[u*7 + v];
                        float w1 = sw1[49 + u*7 + v];
                        float w2 = sw1[98 + u*7 + v];
                        a10.x += rr[v+1]*w0; a10.y += rr[v+2]*w0; a10.z += rr[v+3]*w0; a10.w += rr[v+4]*w0;
                        a11.x += rr[v+1]*w1; a11.y += rr[v+2]*w1; a11.z += rr[v+3]*w1; a11.w += rr[v+4]*w1;
                        a12.x += rr[v+1]*w2; a12.y += rr[v+2]*w2; a12.z += rr[v+3]*w2; a12.w += rr[v+4]*w2;
                    }
                }
            }
            float* o0 = sT + (i0+3)*72 + j0 + 4;
            if (g < 15) {
                *(float4*)o0 = a00; *(float4*)(o0+4968) = a01; *(float4*)(o0+9936) = a02;
                if (two) {
                    float* o1 = o0 + 72;
                    *(float4*)o1 = a10; *(float4*)(o1+4968) = a11; *(float4*)(o1+9936) = a12;
                }
            } else {
                o0[0]=a00.x; o0[1]=a00.y; o0[2]=a00.z;
                o0[4968]=a01.x; o0[4969]=a01.y; o0[4970]=a01.z;
                o0[9936]=a02.x; o0[9937]=a02.y; o0[9938]=a02.z;
                if (two) {
                    float* o1 = o0 + 72;
                    o1[0]=a10.x; o1[1]=a10.y; o1[2]=a10.z;
                    o1[4968]=a11.x; o1[4969]=a11.y; o1[4970]=a11.z;
                    o1[9936]=a12.x; o1[9937]=a12.y; o1[9938]=a12.z;
                }
            }
        }
        __syncthreads();

        // ---- (c) stage2: x += sum_c conv7(t[c], w2[c]) — 2-row x 8-wide ----
        if (tid < 256) {
            int rp = tid >> 3, g = tid & 7;
            int i0 = rp << 1;
            bool two = (i0 + 1 < 63);
            int j0 = g << 3;
            float4 A0a={0,0,0,0}, A0b={0,0,0,0}, A1a={0,0,0,0}, A1b={0,0,0,0};
            #pragma unroll
            for (int c = 0; c < 3; c++) {
                const float* tb = sT + c*4968;
                const float* wc_ = sw2 + c*49;
                #pragma unroll
                for (int rr_ = 0; rr_ < 8; rr_++) {
                    if (rr_ == 7 && !two) break;
                    const float4* rp4 = (const float4*)(tb + (i0+rr_)*72 + j0);
                    float4 Ra = rp4[0], Rb = rp4[1], Rc = rp4[2], Rd = rp4[3];
                    float rr[16] = {Ra.x,Ra.y,Ra.z,Ra.w, Rb.x,Rb.y,Rb.z,Rb.w,
                                    Rc.x,Rc.y,Rc.z,Rc.w, Rd.x,Rd.y,Rd.z,Rd.w};
                    if (rr_ < 7) {
                        #pragma unroll
                        for (int v = 0; v < 7; v++) {
                            float wv = wc_[rr_*7 + v];
                            A0a.x += rr[v+1]*wv; A0a.y += rr[v+2]*wv;
                            A0a.z += rr[v+3]*wv; A0a.w += rr[v+4]*wv;
                            A0b.x += rr[v+5]*wv; A0b.y += rr[v+6]*wv;
                            A0b.z += rr[v+7]*wv; A0b.w += rr[v+8]*wv;
                        }
                    }
                    if (rr_ >= 1) {
                        int u = rr_ - 1;
                        #pragma unroll
                        for (int v = 0; v < 7; v++) {
                            float wv = wc_[u*7 + v];
                            A1a.x += rr[v+1]*wv; A1a.y += rr[v+2]*wv;
                            A1a.z += rr[v+3]*wv; A1a.w += rr[v+4]*wv;
                            A1b.x += rr[v+5]*wv; A1b.y += rr[v+6]*wv;
                            A1b.z += rr[v+7]*wv; A1b.w += rr[v+8]*wv;
                        }
                    }
                }
            }
            float* xo0 = sxp + (i0+1)*68 + j0 + 1;
            xo0[0]+=A0a.x; xo0[1]+=A0a.y; xo0[2]+=A0a.z; xo0[3]+=A0a.w;
            xo0[4]+=A0b.x; xo0[5]+=A0b.y; xo0[6]+=A0b.z;
            if (g < 7) xo0[7]+=A0b.w;
            if (two) {
                float* xo1 = xo0 + 68;
                xo1[0]+=A1a.x; xo1[1]+=A1a.y; xo1[2]+=A1a.z; xo1[3]+=A1a.w;
                xo1[4]+=A1b.x; xo1[5]+=A1b.y; xo1[6]+=A1b.z;
                if (g < 7) xo1[7]+=A1b.w;
            }
        }
        __syncthreads();

        // ---- (d) residual -> srp ----
        #pragma unroll
        for (int p = 0; p < 8; p++) {
            int el = tid + p*T;
            if (el >= 4032) break;
            int i = el >> 6, j = el & 63;
            if (j >= 63) continue;
            const float* xb = sxp + i*68 + j;
            float acc = ska[0]*xb[0] + ska[1]*xb[1] + ska[2]*xb[2]
                      + ska[3]*xb[68] + ska[4]*xb[69] + ska[5]*xb[70]
                      + ska[6]*xb[136] + ska[7]*xb[137] + ska[8]*xb[138];
            srp[(i+3)*72 + j + 4] = fr[p] - acc;
        }
        __syncthreads();

        // ---- (P) P[m][k2] = inv * sum_n r[m,n] conj(W[k2,n]) — 2m x 4k2 ----
        if (tid < 256) {
            int mp = tid >> 3, q = tid & 7;
            int m0 = mp << 1, m1 = m0 + 1;
            int k20 = q << 2;
            const float* r0p = srp + (m0+3)*72 + 4;
            const float* r1p = r0p + 72;
            float4 ar0={0,0,0,0}, ai0={0,0,0,0}, ar1={0,0,0,0}, ai1={0,0,0,0};
            #pragma unroll 7
            for (int n = 0; n < 63; n++) {
                float rv0 = r0p[n], rv1 = r1p[n];
                float4 c = *(const float4*)(sttc + n*36 + k20);
                float4 s = *(const float4*)(stts + n*36 + k20);
                ar0.x += rv0*c.x; ar0.y += rv0*c.y; ar0.z += rv0*c.z; ar0.w += rv0*c.w;
                ai0.x -= rv0*s.x; ai0.y -= rv0*s.y; ai0.z -= rv0*s.z; ai0.w -= rv0*s.w;
                ar1.x += rv1*c.x; ar1.y += rv1*c.y; ar1.z += rv1*c.z; ar1.w += rv1*c.w;
                ai1.x -= rv1*s.x; ai1.y -= rv1*s.y; ai1.z -= rv1*s.z; ai1.w -= rv1*s.w;
            }
            float4 R0 = {ar0.x*inv, ar0.y*inv, ar0.z*inv, ar0.w*inv};
            float4 I0 = {ai0.x*inv, ai0.y*inv, ai0.z*inv, ai0.w*inv};
            *(float4*)(sPr + m0*36 + k20) = R0;
            *(float4*)(sPi + m0*36 + k20) = I0;
            if (m1 < 63) {
                float4 R1 = {ar1.x*inv, ar1.y*inv, ar1.z*inv, ar1.w*inv};
                float4 I1 = {ai1.x*inv, ai1.y*inv, ai1.z*inv, ai1.w*inv};
                *(float4*)(sPr + m1*36 + k20) = R1;
                *(float4*)(sPi + m1*36 + k20) = I1;
            }
        }
        __syncthreads();

        // ---- (C) C[k1][k2] = (inv * sum_m conj(W[k1,m]) P[m][k2]) * wc — 2k1 x 4k2 ----
        if (tid < 256) {
            int kp = tid >> 3, q = tid & 7;
            int k10 = kp << 1, k11 = k10 + 1;
            int k11c = (k11 < 63) ? k11 : 62;
            int k20 = q << 2;
            const float* c0 = sct + k10*68;
            const float* s0 = sst + k10*68;
            const float* c1 = sct + k11c*68;
            const float* s1p = sst + k11c*68;
            float4 ar0={0,0,0,0}, ai0={0,0,0,0}, ar1={0,0,0,0}, ai1={0,0,0,0};
            #pragma unroll 7
            for (int m = 0; m < 63; m++) {
                float cw0 = c0[m], sw0 = s0[m];
                float cw1 = c1[m], sw1v = s1p[m];
                float4 pr = *(const float4*)(sPr + m*36 + k20);
                float4 pi = *(const float4*)(sPi + m*36 + k20);
                ar0.x += cw0*pr.x + sw0*pi.x;  ai0.x += cw0*pi.x - sw0*pr.x;
                ar0.y += cw0*pr.y + sw0*pi.y;  ai0.y += cw0*pi.y - sw0*pr.y;
                ar0.z += cw0*pr.z + sw0*pi.z;  ai0.z += cw0*pi.z - sw0*pr.z;
                ar0.w += cw0*pr.w + sw0*pi.w;  ai0.w += cw0*pi.w - sw0*pr.w;
                ar1.x += cw1*pr.x + sw1v*pi.x;  ai1.x += cw1*pi.x - sw1v*pr.x;
                ar1.y += cw1*pr.y + sw1v*pi.y;  ai1.y += cw1*pi.y - sw1v*pr.y;
                ar1.z += cw1*pr.z + sw1v*pi.z;  ai1.z += cw1*pi.z - sw1v*pr.z;
                ar1.w += cw1*pr.w + sw1v*pi.w;  ai1.w += cw1*pi.w - sw1v*pr.w;
            }
            {
                float4 wr = *(const float4*)(swcr + k10*36 + k20);
                float4 wi = *(const float4*)(swci + k10*36 + k20);
                float4 arv = {ar0.x*inv, ar0.y*inv, ar0.z*inv, ar0.w*inv};
                float4 aiv = {ai0.x*inv, ai0.y*inv, ai0.z*inv, ai0.w*inv};
                float4 cr = {arv.x*wr.x - aiv.x*wi.x, arv.y*wr.y - aiv.y*wi.y,
                             arv.z*wr.z - aiv.z*wi.z, arv.w*wr.w - aiv.w*wi.w};
                float4 ci = {arv.x*wi.x + aiv.x*wr.x, arv.y*wi.y + aiv.y*wr.y,
                             arv.z*wi.z + aiv.z*wr.z, arv.w*wi.w + aiv.w*wr.w};
                *(float4*)(sCr + k10*36 + k20) = cr;
                *(float4*)(sCi + k10*36 + k20) = ci;
            }
            if (k11 < 63) {
                float4 wr = *(const float4*)(swcr + k11*36 + k20);
                float4 wi = *(const float4*)(swci + k11*36 + k20);
                float4 arv = {ar1.x*inv, ar1.y*inv, ar1.z*inv, ar1.w*inv};
                float4 aiv = {ai1.x*inv, ai1.y*inv, ai1.z*inv, ai1.w*inv};
                float4 cr = {arv.x*wr.x - aiv.x*wi.x, arv.y*wr.y - aiv.y*wi.y,
                             arv.z*wr.z - aiv.z*wi.z, arv.w*wr.w - aiv.w*wi.w};
                float4 ci = {arv.x*wi.x + aiv.x*wr.x, arv.y*wi.y + aiv.y*wr.y,
                             arv.z*wi.z + aiv.z*wr.z, arv.w*wi.w + aiv.w*wr.w};
                *(float4*)(sCr + k11*36 + k20) = cr;
                *(float4*)(sCi + k11*36 + k20) = ci;
            }
        }
        __syncthreads();

        // ---- (D) D[m][k2] = inv * sum_k1 W[m,k1] C[k1][k2] — 2m x 4k2 ----
        if (tid < 256) {
            int mp = tid >> 3, q = tid & 7;
            int m0 = mp << 1, m1 = m0 + 1;
            int m1c = (m1 < 63) ? m1 : 62;
            int k20 = q << 2;
            const float* c0 = sct + m0*68;
            const float* s0 = sst + m0*68;
            const float* c1 = sct + m1c*68;
            const float* s1p = sst + m1c*68;
            float4 dr0={0,0,0,0}, di0={0,0,0,0}, dr1={0,0,0,0}, di1={0,0,0,0};
            #pragma unroll 7
            for (int k1 = 0; k1 < 63; k1++) {
                float cw0 = c0[k1], sw0 = s0[k1];
                float cw1 = c1[k1], sw1v = s1p[k1];
                float4 Cr = *(const float4*)(sCr + k1*36 + k20);
                float4 Ci = *(const float4*)(sCi + k1*36 + k20);
                dr0.x += cw0*Cr.x - sw0*Ci.x;  di0.x += cw0*Ci.x + sw0*Cr.x;
                dr0.y += cw0*Cr.y - sw0*Ci.y;  di0.y += cw0*Ci.y + sw0*Cr.y;
                dr0.z += cw0*Cr.z - sw0*Ci.z;  di0.z += cw0*Ci.z + sw0*Cr.z;
                dr0.w += cw0*Cr.w - sw0*Ci.w;  di0.w += cw0*Ci.w + sw0*Cr.w;
                dr1.x += cw1*Cr.x - sw1v*Ci.x;  di1.x += cw1*Ci.x + sw1v*Cr.x;
                dr1.y += cw1*Cr.y - sw1v*Ci.y;  di1.y += cw1*Ci.y + sw1v*Cr.y;
                dr1.z += cw1*Cr.z - sw1v*Ci.z;  di1.z += cw1*Ci.z + sw1v*Cr.z;
                dr1.w += cw1*Cr.w - sw1v*Ci.w;  di1.w += cw1*Ci.w + sw1v*Cr.w;
            }
            float4 R0 = {dr0.x*inv, dr0.y*inv, dr0.z*inv, dr0.w*inv};
            float4 I0 = {di0.x*inv, di0.y*inv, di0.z*inv, di0.w*inv};
            *(float4*)(sDr + m0*36 + k20) = R0;
            *(float4*)(sDi + m0*36 + k20) = I0;
            if (m1 < 63) {
                float4 R1 = {dr1.x*inv, dr1.y*inv, dr1.z*inv, dr1.w*inv};
                float4 I1 = {di1.x*inv, di1.y*inv, di1.z*inv, di1.w*inv};
                *(float4*)(sDr + m1*36 + k20) = R1;
                *(float4*)(sDi + m1*36 + k20) = I1;
            }
        }
        __syncthreads();

        // ---- (h) x[m,n] += inv*(Dr[m,0] + 2*sum Re(D[m,k2] W[k2,n])) — 2m x 4n ----
        {
            int mp = tid >> 4, g = tid & 15;
            int m0 = mp << 1, m1 = m0 + 1;
            bool two = (m1 < 63);
            int n0 = g << 2;
            const float* d0r = sDr + m0*36;
            const float* d0i = sDi + m0*36;
            const float* d1r = sDr + m1*36;
            const float* d1i = sDi + m1*36;
            float4 A0 = {0,0,0,0}, A1 = {0,0,0,0};
            float b0v = d0r[0], b1v = d1r[0];
            #pragma unroll 8
            for (int k2 = 1; k2 < 32; k2++) {
                float4 c4 = *(const float4*)(sct + k2*68 + n0);
                float4 s4 = *(const float4*)(sst + k2*68 + n0);
                float e0r = d0r[k2]*2.f, e0i = d0i[k2]*2.f;
                float e1r = d1r[k2]*2.f, e1i = d1i[k2]*2.f;
                A0.x += e0r*c4.x - e0i*s4.x;
                A0.y += e0r*c4.y - e0i*s4.y;
                A0.z += e0r*c4.z - e0i*s4.z;
                A0.w += e0r*c4.w - e0i*s4.w;
                A1.x += e1r*c4.x - e1i*s4.x;
                A1.y += e1r*c4.y - e1i*s4.y;
                A1.z += e1r*c4.z - e1i*s4.z;
                A1.w += e1r*c4.w - e1i*s4.w;
            }
            float* xo0 = sxp + (m0+1)*68 + n0 + 1;
            xo0[0] += (b0v + A0.x)*inv;
            xo0[1] += (b0v + A0.y)*inv;
            xo0[2] += (b0v + A0.z)*inv;
            if (g < 15) xo0[3] += (b0v + A0.w)*inv;
            if (two) {
                float* xo1 = sxp + (m1+1)*68 + n0 + 1;
                xo1[0] += (b1v + A1.x)*inv;
                xo1[1] += (b1v + A1.y)*inv;
                xo1[2] += (b1v + A1.z)*inv;
                if (g < 15) xo1[3] += (b1v + A1.w)*inv;
            }
        }
        __syncthreads();
    }

    // ---- final residual + sum of squares ----
    float loc = 0.f;
    #pragma unroll
    for (int p = 0; p < 8; p++) {
        int el = tid + p*T;
        if (el >= 4032) break;
        int i = el >> 6, j = el & 63;
        if (j >= 63) continue;
        const float* xb = sxp + i*68 + j;
        float acc = ska[0]*xb[0] + ska[1]*xb[1] + ska[2]*xb[2]
                  + ska[3]*xb[68] + ska[4]*xb[69] + ska[5]*xb[70]
                  + ska[6]*xb[136] + ska[7]*xb[137] + ska[8]*xb[138];
        float v = fr[p] - acc;
        loc += v * v;
    }
    #pragma unroll
    for (int off = 16; off; off >>= 1)
        loc += __shfl_xor_sync(0xFFFFFFFFu, loc, off);
    __shared__ float wsum[16];
    int wid = tid >> 5;
    if ((tid & 31) == 0) wsum[wid] = loc;
    __syncthreads();
    if (tid == 0) {
        float s = 0.f;
        #pragma unroll
        for (int w = 0; w < 16; w++) s += wsum[w];
        g_blocksum[b] = s;
    }
}

__global__ void final_reduce_kernel(float* __restrict__ out) {
    __shared__ float s[BATCH];
    s[threadIdx.x] = g_blocksum[threadIdx.x];
    __syncthreads();
    for (int st = BATCH/2; st > 0; st >>= 1) {
        if (threadIdx.x < st) s[threadIdx.x] += s[threadIdx.x + st];
        __syncthreads();
    }
    if (threadIdx.x == 0) out[0] = sqrtf(s[0]) / 256.0f;
}

// ---------------- host ----------------
extern "C" void kernel_launch(void* const* d_in, const int* in_sizes, int n_in,
                              void* d_out, int out_size) {
    const float* x      = (const float*)d_in[0];
    const float* f      = (const float*)d_in[1];
    const float* kA     = (const float*)d_in[2];
    const float* fc1_w1 = (const float*)d_in[3];
    const float* fc1_b1 = (const float*)d_in[4];
    const float* fc1_w2 = (const float*)d_in[5];
    const float* fc1_b2 = (const float*)d_in[6];
    const float* fc2_w1 = (const float*)d_in[7];
    const float* fc2_b1 = (const float*)d_in[8];
    const float* fc2_w2 = (const float*)d_in[9];
    const float* fc2_b2 = (const float*)d_in[10];
    const float* ct1_w  = (const float*)d_in[11];
    const float* ct1_b  = (const float*)d_in[12];
    const float* ct2_w  = (const float*)d_in[13];
    const float* ct2_b  = (const float*)d_in[14];
    const float* ct3_w  = (const float*)d_in[15];
    const float* ct3_b  = (const float*)d_in[16];
    const float* ct4_w  = (const float*)d_in[17];
    const float* ct4_b  = (const float*)d_in[18];
    const float* ct5_w  = (const float*)d_in[19];
    const float* ct5_b  = (const float*)d_in[20];
    float* out = (float*)d_out;

    cudaFuncSetAttribute(solver_kernel, cudaFuncAttributeMaxDynamicSharedMemorySize,
                         SMEM_FLOATS * (int)sizeof(float));
    cudaFuncSetAttribute(ctchain_kernel, cudaFuncAttributeMaxDynamicSharedMemorySize,
                         CT_SMEM_FLOATS * (int)sizeof(float));

    hyper_kernel<<<BATCH, 256>>>(kA, fc1_w1, fc1_b1, fc1_w2, fc1_b2,
                                 fc2_w1, fc2_b1, fc2_w2, fc2_b2);
    ctchain_kernel<<<BATCH, 512, CT_SMEM_FLOATS * sizeof(float)>>>(kA, ct1_w, ct1_b, ct2_w, ct2_b,
                                                                   ct3_w, ct3_b, ct4_w, ct4_b);
    init_tw_kernel<<<(63*68 + 255)/256, 256>>>();
    solver_kernel<<<BATCH, 512, SMEM_FLOATS * sizeof(float)>>>(x, f, kA, ct5_w, ct5_b);
    final_reduce_kernel<<<1, BATCH>>>(out);
}

// round 16
// speedup vs baseline: 1.1450x; 1.1450x over previous
#include <cuda_runtime.h>
#include <math.h>

#define NN 63
#define NP (NN*NN)          // 3969
#define BATCH 256
#define KS 7
#define ML 3

// ---------------- device scratch ----------------
__device__ float g_cosT[63*68];   // [k][n] rows padded to 68, cols 63..67 = 0
__device__ float g_sinT[63*68];
__device__ float g_cosTT[63*36];  // transposed [n][k2<32], stride 36
__device__ float g_sinTT[63*36];
__device__ float g_w1[BATCH*147];
__device__ float g_w2[BATCH*147];
__device__ float g_a4[BATCH*1089*32];   // [b][pix][ch]
__device__ float g_blocksum[BATCH];

__device__ __forceinline__ float gelu_exact(float v) {
    return v * 0.5f * (1.0f + erff(v * 0.70710678118654752f));
}

__global__ void init_tw_kernel() {
    int idx = blockIdx.x * blockDim.x + threadIdx.x;
    if (idx < 63*68) {
        int k = idx / 68, n = idx % 68;
        if (n < 63) {
            float ang = 6.28318530717958647692f * (float)((k * n) % NN) / 63.0f;
            g_cosT[idx] = cosf(ang);
            g_sinT[idx] = sinf(ang);
        } else { g_cosT[idx] = 0.f; g_sinT[idx] = 0.f; }
    }
    if (idx < 63*36) {
        int n = idx / 36, k2 = idx % 36;
        if (k2 < 32) {
            float ang = 6.28318530717958647692f * (float)((k2 * n) % NN) / 63.0f;
            g_cosTT[idx] = cosf(ang);
            g_sinTT[idx] = sinf(ang);
        } else { g_cosTT[idx] = 0.f; g_sinTT[idx] = 0.f; }
    }
}

// ---------------- hypernet ----------------
__global__ void hyper_kernel(const float* __restrict__ kA,
                             const float* __restrict__ w1a, const float* __restrict__ b1a,
                             const float* __restrict__ w2a, const float* __restrict__ b2a,
                             const float* __restrict__ w1b, const float* __restrict__ b1b,
                             const float* __restrict__ w2b, const float* __restrict__ b2b) {
    int b = blockIdx.x;
    __shared__ float a[9], h1[100], h2[100];
    int t = threadIdx.x;
    if (t < 9) a[t] = kA[b*9 + t];
    __syncthreads();
    if (t < 100) {
        float s = b1a[t];
        #pragma unroll
        for (int i = 0; i < 9; i++) s += a[i] * w1a[i*100 + t];
        h1[t] = gelu_exact(s);
    } else if (t < 200) {
        int h = t - 100;
        float s = b1b[h];
        #pragma unroll
        for (int i = 0; i < 9; i++) s += a[i] * w1b[i*100 + h];
        h2[h] = gelu_exact(s);
    }
    __syncthreads();
    for (int o = t; o < 147; o += blockDim.x) {
        float s1 = b2a[o], s2 = b2b[o];
        for (int h = 0; h < 100; h++) {
            s1 += h1[h] * w2a[h*147 + o];
            s2 += h2[h] * w2b[h*147 + o];
        }
        g_w1[b*147 + o] = s1;
        g_w2[b*147 + o] = s2;
    }
}

// ---------------- fused ConvTranspose chain ct1..ct4 ----------------
__device__ __forceinline__ void load_ctw(const float* __restrict__ w,
                                         const float* __restrict__ bias,
                                         float* s_w, float* s_bias, int tid) {
    for (int idx = tid; idx < 9216; idx += 512) {
        int i = idx & 31, o = (idx >> 5) & 31, k = idx >> 10;
        s_w[k*1040 + (o>>3)*260 + (o&7)*32 + i] = w[(i*32 + o)*9 + k];
    }
    if (tid < 32) s_bias[tid] = bias[tid];
}

__device__ __forceinline__ void ct_store(float* __restrict__ ob, const float* acc) {
    float4 o0 = {gelu_exact(acc[0]), gelu_exact(acc[1]), gelu_exact(acc[2]), gelu_exact(acc[3])};
    float4 o1 = {gelu_exact(acc[4]), gelu_exact(acc[5]), gelu_exact(acc[6]), gelu_exact(acc[7])};
    *(float4*)ob = o0;
    *(float4*)(ob + 4) = o1;
}

// R8 structure with PIXEL-PAIR blocking: each thread computes (y,x) and (y,x+2)
// (same parity class -> identical tap list & weight addresses -> weight loads
//  amortized over 2 outputs). Singleton pairs (even-series tail) predicate off
//  the second store; their extra loads stay inside block smem (dead buffer).
template<int IN_H>
__device__ void ct_midstage(const float* __restrict__ s_in, const float* __restrict__ s_w,
                            const float* __restrict__ s_bias, float* __restrict__ out, int tid) {
    constexpr int OUT_H = 2*IN_H - 1;
    constexpr int EC = (OUT_H + 1) / 2;       // even-column count
    constexpr int OC = OUT_H - EC;            // odd-column count
    constexpr int PE = (EC + 1) / 2;          // even-series pairs (last is singleton)
    constexpr int PO = (OC + 1) / 2;          // odd-series pairs (always full here)
    constexpr int PPR = PE + PO;              // pairs per row
    constexpr int ITEMS = OUT_H * PPR * 4;
    const float4* in4 = (const float4*)s_in;
    const float4* w4  = (const float4*)s_w;
    for (int it = tid; it < ITEMS; it += 512) {
        int og = it & 3, t = it >> 2;
        int y = t / PPR, pr = t % PPR;
        int x; bool valid2;
        if (pr < PE) { x = 4*pr;            valid2 = (x + 2) < OUT_H; }
        else         { x = 1 + 4*(pr - PE); valid2 = true; }
        float accA[8], accB[8];
        #pragma unroll
        for (int ol = 0; ol < 8; ol++) { accA[ol] = s_bias[og*8 + ol]; accB[ol] = accA[ol]; }
        int kys[2], iys[2], nky, kxs[2], ixs[2], nkx;
        if (y & 1) { nky=2; kys[0]=0; iys[0]=(y+1)>>1; kys[1]=2; iys[1]=(y-1)>>1; }
        else       { nky=1; kys[0]=1; iys[0]=y>>1; }
        if (x & 1) { nkx=2; kxs[0]=0; ixs[0]=(x+1)>>1; kxs[1]=2; ixs[1]=(x-1)>>1; }
        else       { nkx=1; kxs[0]=1; ixs[0]=x>>1; }
        for (int p = 0; p < nky; p++)
            for (int q = 0; q < nkx; q++) {
                int base4 = (iys[p]*IN_H + ixs[q]) * 8;
                const float4* wrow = w4 + (kys[p]*3 + kxs[q])*260 + og*65;
                #pragma unroll
                for (int c4 = 0; c4 < 8; c4++) {
                    float4 va = in4[base4 + c4];
                    float4 vb = in4[base4 + 8 + c4];   // second pixel: ix+1
                    #pragma unroll
                    for (int ol = 0; ol < 8; ol++) {
                        float4 wv = wrow[ol*8 + c4];
                        accA[ol] += va.x*wv.x + va.y*wv.y + va.z*wv.z + va.w*wv.w;
                        accB[ol] += vb.x*wv.x + vb.y*wv.y + vb.z*wv.z + vb.w*wv.w;
                    }
                }
            }
        int pixA = y*OUT_H + x;
        ct_store(out + pixA*32 + og*8, accA);
        if (valid2) ct_store(out + (pixA + 2)*32 + og*8, accB);
    }
}

__global__ void __launch_bounds__(512) ctchain_kernel(
    const float* __restrict__ kA,
    const float* __restrict__ w1c, const float* __restrict__ b1c,
    const float* __restrict__ w2c, const float* __restrict__ b2c,
    const float* __restrict__ w3c, const float* __restrict__ b3c,
    const float* __restrict__ w4c, const float* __restrict__ b4c) {
    extern __shared__ float cs[];
    float* s_w    = cs;               // 9360
    float* B1     = cs + 9360;        // 9248
    float* B2     = B1 + 9248;        // 2592
    float* s_a    = B2 + 2592;        // 16
    float* s_bias = s_a + 16;         // 32
    int b = blockIdx.x, tid = threadIdx.x;

    if (tid < 9) s_a[tid] = kA[b*9 + tid];
    load_ctw(w2c, b2c, s_w, s_bias, tid);
    __syncthreads();

    for (int el = tid; el < 800; el += 512) {
        int pix = el >> 5, o = el & 31;
        int y = pix / 5, x = pix % 5;
        float acc = b1c[o];
        int kys[2], iys[2], nky, kxs[2], ixs[2], nkx;
        if (y & 1) { nky=2; kys[0]=0; iys[0]=(y+1)>>1; kys[1]=2; iys[1]=(y-1)>>1; }
        else       { nky=1; kys[0]=1; iys[0]=y>>1; }
        if (x & 1) { nkx=2; kxs[0]=0; ixs[0]=(x+1)>>1; kxs[1]=2; ixs[1]=(x-1)>>1; }
        else       { nkx=1; kxs[0]=1; ixs[0]=x>>1; }
        for (int p = 0; p < nky; p++)
            for (int q = 0; q < nkx; q++)
                acc += s_a[iys[p]*3 + ixs[q]] * w1c[o*9 + kys[p]*3 + kxs[q]];
        B1[pix*32 + o] = gelu_exact(acc);
    }
    __syncthreads();

    ct_midstage<5>(B1, s_w, s_bias, B2, tid);
    __syncthreads();
    load_ctw(w3c, b3c, s_w, s_bias, tid);
    __syncthreads();
    ct_midstage<9>(B2, s_w, s_bias, B1, tid);
    __syncthreads();
    load_ctw(w4c, b4c, s_w, s_bias, tid);
    __syncthreads();
    ct_midstage<17>(B1, s_w, s_bias, g_a4 + (size_t)b*1089*32, tid);
}

// ---------------- persistent per-sample solver (R8/R12 verbatim) ----------------
#define O_SXP 0                      // 65x68 = 4420
#define O_SRP 4420                   // 69x72 = 4968
#define O_T   9388                   // 3*4968 = 14904 (ct5 staging 7938 fits)
#define O_PR  24292                  // [m][36] = 2268
#define O_PI  26560
#define O_CR  28828                  // [k1][36] = 2268
#define O_CI  31096
#define O_DR  33364                  // [m][36] = 2268
#define O_DI  35632
#define O_WCR 37900                  // [k1][36] = 2268
#define O_WCI 40168
#define O_CT  42436                  // [k][68] = 4284
#define O_ST  46720
#define O_TTC 51004                  // [n][36] = 2268
#define O_TTS 53272
#define O_W5  55540                  // 576
#define O_W1  56116                  // 160
#define O_W2  56276
#define O_KA  56436
#define SMEM_FLOATS 56452            // 225808 B

__global__ void __launch_bounds__(512) solver_kernel(const float* __restrict__ x_in,
                              const float* __restrict__ f_in,
                              const float* __restrict__ kA,
                              const float* __restrict__ w5, const float* __restrict__ b5) {
    extern __shared__ float sm[];
    float* sxp  = sm + O_SXP;
    float* srp  = sm + O_SRP;
    float* sT   = sm + O_T;
    float* sPr  = sm + O_PR;
    float* sPi  = sm + O_PI;
    float* sCr  = sm + O_CR;
    float* sCi  = sm + O_CI;
    float* sDr  = sm + O_DR;
    float* sDi  = sm + O_DI;
    float* swcr = sm + O_WCR;
    float* swci = sm + O_WCI;
    float* sct  = sm + O_CT;
    float* sst  = sm + O_ST;
    float* sttc = sm + O_TTC;
    float* stts = sm + O_TTS;
    float* sw5  = sm + O_W5;
    float* sw1  = sm + O_W1;
    float* sw2  = sm + O_W2;
    float* ska  = sm + O_KA;

    int b = blockIdx.x, tid = threadIdx.x;
    const int T = 512;
    const float inv = 0.12598815766974242f;  // 1/sqrt(63)

    // ---- init ----
    float fr[8];
    #pragma unroll
    for (int p = 0; p < 8; p++) {
        int el = tid + p*T;
        fr[p] = 0.f;
        if (el < 4032) {
            int i = el >> 6, j = el & 63;
            if (j < 63) {
                fr[p] = f_in[b*NP + i*NN + j];
                sxp[(i+1)*68 + (j+1)] = x_in[b*NP + i*NN + j];
            }
        }
    }
    for (int el = tid; el < 63*68; el += T) { sct[el] = g_cosT[el]; sst[el] = g_sinT[el]; }
    for (int el = tid; el < 63*36; el += T) { sttc[el] = g_cosTT[el]; stts[el] = g_sinTT[el]; }
    for (int c = tid; c < 65; c += T) {
        sxp[c] = (c == 64) ? 1.f : 0.f;
        sxp[64*68 + c] = 1.f;
    }
    for (int r = tid; r < 65; r += T) {
        sxp[r*68] = (r == 64) ? 1.f : 0.f;
        sxp[r*68 + 64] = 1.f;
    }
    for (int idx = tid; idx < 576; idx += T) {
        int k = idx / 64, r = idx & 63, o = r >> 5, i = r & 31;
        sw5[idx] = w5[i*18 + o*9 + k];
    }
    if (tid < 9) ska[tid] = kA[b*9 + tid];
    for (int el = tid; el < 147; el += T) {
        sw1[el] = g_w1[b*147 + el];
        sw2[el] = g_w2[b*147 + el];
    }
    __syncthreads();

    // ---- ct5 fused: h flat [2][63*63] into sT staging ----
    {
        float b0 = b5[0], b1 = b5[1];
        const float4* s_w4 = (const float4*)sw5;
        const float4* gin = (const float4*)(g_a4 + (size_t)b * 1089 * 32);
        for (int pix = tid; pix < NP; pix += T) {
            int y = pix / NN, x = pix % NN;
            float acc0 = b0, acc1 = b1;
            int kys[2], iys[2], nky, kxs[2], ixs[2], nkx;
            if (y & 1) { nky=1; kys[0]=1; iys[0]=(y+1)>>1; }
            else       { nky=2; kys[0]=0; iys[0]=(y+2)>>1; kys[1]=2; iys[1]=y>>1; }
            if (x & 1) { nkx=1; kxs[0]=1; ixs[0]=(x+1)>>1; }
            else       { nkx=2; kxs[0]=0; ixs[0]=(x+2)>>1; kxs[1]=2; ixs[1]=x>>1; }
            for (int p = 0; p < nky; p++)
                for (int q = 0; q < nkx; q++) {
                    int base4 = (iys[p]*33 + ixs[q]) * 8;
                    int kk = kys[p]*3 + kxs[q];
                    #pragma unroll
                    for (int c4 = 0; c4 < 8; c4++) {
                        float4 v = __ldg(gin + base4 + c4);
                        float4 w0 = s_w4[kk*16 + c4];
                        float4 w1 = s_w4[kk*16 + 8 + c4];
                        acc0 += v.x*w0.x + v.y*w0.y + v.z*w0.z + v.w*w0.w;
                        acc1 += v.x*w1.x + v.y*w1.y + v.z*w1.z + v.w*w1.w;
                    }
                }
            sT[pix] = acc0;
            sT[NP + pix] = acc1;
        }
    }
    __syncthreads();
    for (int el = tid; el < 2016; el += T) {
        int k1 = el >> 5, k2 = el & 31;
        int p = k1*63 + k2;
        swcr[k1*36 + k2] = sT[2*p];
        swci[k1*36 + k2] = sT[2*p + 1];
    }
    __syncthreads();
    for (int el = tid; el < 14904; el += T) sT[el] = 0.f;
    for (int el = tid; el < 4968; el += T) srp[el] = 0.f;
    __syncthreads();

    for (int iter = 0; iter < 5; iter++) {
        // ---- (a) residual -> srp ----
        #pragma unroll
        for (int p = 0; p < 8; p++) {
            int el = tid + p*T;
            if (el >= 4032) break;
            int i = el >> 6, j = el & 63;
            if (j >= 63) continue;
            const float* xb = sxp + i*68 + j;
            float acc = ska[0]*xb[0] + ska[1]*xb[1] + ska[2]*xb[2]
                      + ska[3]*xb[68] + ska[4]*xb[69] + ska[5]*xb[70]
                      + ska[6]*xb[136] + ska[7]*xb[137] + ska[8]*xb[138];
            srp[(i+3)*72 + j + 4] = fr[p] - acc;
        }
        __syncthreads();

        // ---- (b) stage1: t[c] = conv7(r, w1[c]) — 2-row blocked, 3 channels ----
        {
            int rpair = tid >> 4, g = tid & 15;
            int i0 = rpair << 1;
            bool two = (i0 + 1 < 63);
            int j0 = g << 2;
            float4 a00={0,0,0,0}, a01={0,0,0,0}, a02={0,0,0,0};
            float4 a10={0,0,0,0}, a11={0,0,0,0}, a12={0,0,0,0};
            #pragma unroll
            for (int rr_ = 0; rr_ < 8; rr_++) {
                if (rr_ == 7 && !two) break;
                const float4* rp4 = (const float4*)(srp + (i0+rr_)*72 + j0);
                float4 Ra = rp4[0], Rb = rp4[1], Rc = rp4[2];
                float rr[12] = {Ra.x,Ra.y,Ra.z,Ra.w, Rb.x,Rb.y,Rb.z,Rb.w, Rc.x,Rc.y,Rc.z,Rc.w};
                if (rr_ < 7) {
                    #pragma unroll
                    for (int v = 0; v < 7; v++) {
                        float w0 = sw1[rr_*7 + v];
                        float w1 = sw1[49 + rr_*7 + v];
                        float w2 = sw1[98 + rr_*7 + v];
                        a00.x += rr[v+1]*w0; a00.y += rr[v+2]*w0; a00.z += rr[v+3]*w0; a00.w += rr[v+4]*w0;
                        a01.x += rr[v+1]*w1; a01.y += rr[v+2]*w1; a01.z += rr[v+3]*w1; a01.w += rr[v+4]*w1;
                        a02.x += rr[v+1]*w2; a02.y += rr[v+2]*w2; a02.z += rr[v+3]*w2; a02.w += rr[v+4]*w2;
                    }
                }
                if (rr_ >= 1) {
                    int u = rr_ - 1;
                    #pragma unroll
                    for (int v = 0; v < 7; v++) {
                        float w0 = sw1[u*7 + v];
                        float w1 = sw1[49 + u*7 + v];
                        float w2 = sw1[98 + u*7 + v];
                        a10.x += rr[v+1]*w0; a10.y += rr[v+2]*w0; a10.z += rr[v+3]*w0; a10.w += rr[v+4]*w0;
                        a11.x += rr[v+1]*w1; a11.y += rr[v+2]*w1; a11.z += rr[v+3]*w1; a11.w += rr[v+4]*w1;
                        a12.x += rr[v+1]*w2; a12.y += rr[v+2]*w2; a12.z += rr[v+3]*w2; a12.w += rr[v+4]*w2;
                    }
                }
            }
            float* o0 = sT + (i0+3)*72 + j0 + 4;
            if (g < 15) {
                *(float4*)o0 = a00; *(float4*)(o0+4968) = a01; *(float4*)(o0+9936) = a02;
                if (two) {
                    float* o1 = o0 + 72;
                    *(float4*)o1 = a10; *(float4*)(o1+4968) = a11; *(float4*)(o1+9936) = a12;
                }
            } else {
                o0[0]=a00.x; o0[1]=a00.y; o0[2]=a00.z;
                o0[4968]=a01.x; o0[4969]=a01.y; o0[4970]=a01.z;
                o0[9936]=a02.x; o0[9937]=a02.y; o0[9938]=a02.z;
                if (two) {
                    float* o1 = o0 + 72;
                    o1[0]=a10.x; o1[1]=a10.y; o1[2]=a10.z;
                    o1[4968]=a11.x; o1[4969]=a11.y; o1[4970]=a11.z;
                    o1[9936]=a12.x; o1[9937]=a12.y; o1[9938]=a12.z;
                }
            }
        }
        __syncthreads();

        // ---- (c) stage2: x += sum_c conv7(t[c], w2[c]) — 2-row x 8-wide ----
        if (tid < 256) {
            int rp = tid >> 3, g = tid & 7;
            int i0 = rp << 1;
            bool two = (i0 + 1 < 63);
            int j0 = g << 3;
            float4 A0a={0,0,0,0}, A0b={0,0,0,0}, A1a={0,0,0,0}, A1b={0,0,0,0};
            #pragma unroll
            for (int c = 0; c < 3; c++) {
                const float* tb = sT + c*4968;
                const float* wc_ = sw2 + c*49;
                #pragma unroll
                for (int rr_ = 0; rr_ < 8; rr_++) {
                    if (rr_ == 7 && !two) break;
                    const float4* rp4 = (const float4*)(tb + (i0+rr_)*72 + j0);
                    float4 Ra = rp4[0], Rb = rp4[1], Rc = rp4[2], Rd = rp4[3];
                    float rr[16] = {Ra.x,Ra.y,Ra.z,Ra.w, Rb.x,Rb.y,Rb.z,Rb.w,
                                    Rc.x,Rc.y,Rc.z,Rc.w, Rd.x,Rd.y,Rd.z,Rd.w};
                    if (rr_ < 7) {
                        #pragma unroll
                        for (int v = 0; v < 7; v++) {
                            float wv = wc_[rr_*7 + v];
                            A0a.x += rr[v+1]*wv; A0a.y += rr[v+2]*wv;
                            A0a.z += rr[v+3]*wv; A0a.w += rr[v+4]*wv;
                            A0b.x += rr[v+5]*wv; A0b.y += rr[v+6]*wv;
                            A0b.z += rr[v+7]*wv; A0b.w += rr[v+8]*wv;
                        }
                    }
                    if (rr_ >= 1) {
                        int u = rr_ - 1;
                        #pragma unroll
                        for (int v = 0; v < 7; v++) {
                            float wv = wc_[u*7 + v];
                            A1a.x += rr[v+1]*wv; A1a.y += rr[v+2]*wv;
                            A1a.z += rr[v+3]*wv; A1a.w += rr[v+4]*wv;
                            A1b.x += rr[v+5]*wv; A1b.y += rr[v+6]*wv;
                            A1b.z += rr[v+7]*wv; A1b.w += rr[v+8]*wv;
                        }
                    }
                }
            }
            float* xo0 = sxp + (i0+1)*68 + j0 + 1;
            xo0[0]+=A0a.x; xo0[1]+=A0a.y; xo0[2]+=A0a.z; xo0[3]+=A0a.w;
            xo0[4]+=A0b.x; xo0[5]+=A0b.y; xo0[6]+=A0b.z;
            if (g < 7) xo0[7]+=A0b.w;
            if (two) {
                float* xo1 = xo0 + 68;
                xo1[0]+=A1a.x; xo1[1]+=A1a.y; xo1[2]+=A1a.z; xo1[3]+=A1a.w;
                xo1[4]+=A1b.x; xo1[5]+=A1b.y; xo1[6]+=A1b.z;
                if (g < 7) xo1[7]+=A1b.w;
            }
        }
        __syncthreads();

        // ---- (d) residual -> srp ----
        #pragma unroll
        for (int p = 0; p < 8; p++) {
            int el = tid + p*T;
            if (el >= 4032) break;
            int i = el >> 6, j = el & 63;
            if (j >= 63) continue;
            const float* xb = sxp + i*68 + j;
            float acc = ska[0]*xb[0] + ska[1]*xb[1] + ska[2]*xb[2]
                      + ska[3]*xb[68] + ska[4]*xb[69] + ska[5]*xb[70]
                      + ska[6]*xb[136] + ska[7]*xb[137] + ska[8]*xb[138];
            srp[(i+3)*72 + j + 4] = fr[p] - acc;
        }
        __syncthreads();

        // ---- (P) P[m][k2] = inv * sum_n r[m,n] conj(W[k2,n]) — 2m x 4k2 ----
        if (tid < 256) {
            int mp = tid >> 3, q = tid & 7;
            int m0 = mp << 1, m1 = m0 + 1;
            int k20 = q << 2;
            const float* r0p = srp + (m0+3)*72 + 4;
            const float* r1p = r0p + 72;
            float4 ar0={0,0,0,0}, ai0={0,0,0,0}, ar1={0,0,0,0}, ai1={0,0,0,0};
            #pragma unroll 7
            for (int n = 0; n < 63; n++) {
                float rv0 = r0p[n], rv1 = r1p[n];
                float4 c = *(const float4*)(sttc + n*36 + k20);
                float4 s = *(const float4*)(stts + n*36 + k20);
                ar0.x += rv0*c.x; ar0.y += rv0*c.y; ar0.z += rv0*c.z; ar0.w += rv0*c.w;
                ai0.x -= rv0*s.x; ai0.y -= rv0*s.y; ai0.z -= rv0*s.z; ai0.w -= rv0*s.w;
                ar1.x += rv1*c.x; ar1.y += rv1*c.y; ar1.z += rv1*c.z; ar1.w += rv1*c.w;
                ai1.x -= rv1*s.x; ai1.y -= rv1*s.y; ai1.z -= rv1*s.z; ai1.w -= rv1*s.w;
            }
            float4 R0 = {ar0.x*inv, ar0.y*inv, ar0.z*inv, ar0.w*inv};
            float4 I0 = {ai0.x*inv, ai0.y*inv, ai0.z*inv, ai0.w*inv};
            *(float4*)(sPr + m0*36 + k20) = R0;
            *(float4*)(sPi + m0*36 + k20) = I0;
            if (m1 < 63) {
                float4 R1 = {ar1.x*inv, ar1.y*inv, ar1.z*inv, ar1.w*inv};
                float4 I1 = {ai1.x*inv, ai1.y*inv, ai1.z*inv, ai1.w*inv};
                *(float4*)(sPr + m1*36 + k20) = R1;
                *(float4*)(sPi + m1*36 + k20) = I1;
            }
        }
        __syncthreads();

        // ---- (C) C[k1][k2] = (inv * sum_m conj(W[k1,m]) P[m][k2]) * wc — 2k1 x 4k2 ----
        if (tid < 256) {
            int kp = tid >> 3, q = tid & 7;
            int k10 = kp << 1, k11 = k10 + 1;
            int k11c = (k11 < 63) ? k11 : 62;
            int k20 = q << 2;
            const float* c0 = sct + k10*68;
            const float* s0 = sst + k10*68;
            const float* c1 = sct + k11c*68;
            const float* s1p = sst + k11c*68;
            float4 ar0={0,0,0,0}, ai0={0,0,0,0}, ar1={0,0,0,0}, ai1={0,0,0,0};
            #pragma unroll 7
            for (int m = 0; m < 63; m++) {
                float cw0 = c0[m], sw0 = s0[m];
                float cw1 = c1[m], sw1v = s1p[m];
                float4 pr = *(const float4*)(sPr + m*36 + k20);
                float4 pi = *(const float4*)(sPi + m*36 + k20);
                ar0.x += cw0*pr.x + sw0*pi.x;  ai0.x += cw0*pi.x - sw0*pr.x;
                ar0.y += cw0*pr.y + sw0*pi.y;  ai0.y += cw0*pi.y - sw0*pr.y;
                ar0.z += cw0*pr.z + sw0*pi.z;  ai0.z += cw0*pi.z - sw0*pr.z;
                ar0.w += cw0*pr.w + sw0*pi.w;  ai0.w += cw0*pi.w - sw0*pr.w;
                ar1.x += cw1*pr.x + sw1v*pi.x;  ai1.x += cw1*pi.x - sw1v*pr.x;
                ar1.y += cw1*pr.y + sw1v*pi.y;  ai1.y += cw1*pi.y - sw1v*pr.y;
                ar1.z += cw1*pr.z + sw1v*pi.z;  ai1.z += cw1*pi.z - sw1v*pr.z;
                ar1.w += cw1*pr.w + sw1v*pi.w;  ai1.w += cw1*pi.w - sw1v*pr.w;
            }
            {
                float4 wr = *(const float4*)(swcr + k10*36 + k20);
                float4 wi = *(const float4*)(swci + k10*36 + k20);
                float4 arv = {ar0.x*inv, ar0.y*inv, ar0.z*inv, ar0.w*inv};
                float4 aiv = {ai0.x*inv, ai0.y*inv, ai0.z*inv, ai0.w*inv};
                float4 cr = {arv.x*wr.x - aiv.x*wi.x, arv.y*wr.y - aiv.y*wi.y,
                             arv.z*wr.z - aiv.z*wi.z, arv.w*wr.w - aiv.w*wi.w};
                float4 ci = {arv.x*wi.x + aiv.x*wr.x, arv.y*wi.y + aiv.y*wr.y,
                             arv.z*wi.z + aiv.z*wr.z, arv.w*wi.w + aiv.w*wr.w};
                *(float4*)(sCr + k10*36 + k20) = cr;
                *(float4*)(sCi + k10*36 + k20) = ci;
            }
            if (k11 < 63) {
                float4 wr = *(const float4*)(swcr + k11*36 + k20);
                float4 wi = *(const float4*)(swci + k11*36 + k20);
                float4 arv = {ar1.x*inv, ar1.y*inv, ar1.z*inv, ar1.w*inv};
                float4 aiv = {ai1.x*inv, ai1.y*inv, ai1.z*inv, ai1.w*inv};
                float4 cr = {arv.x*wr.x - aiv.x*wi.x, arv.y*wr.y - aiv.y*wi.y,
                             arv.z*wr.z - aiv.z*wi.z, arv.w*wr.w - aiv.w*wi.w};
                float4 ci = {arv.x*wi.x + aiv.x*wr.x, arv.y*wi.y + aiv.y*wr.y,
                             arv.z*wi.z + aiv.z*wr.z, arv.w*wi.w + aiv.w*wr.w};
                *(float4*)(sCr + k11*36 + k20) = cr;
                *(float4*)(sCi + k11*36 + k20) = ci;
            }
        }
        __syncthreads();

        // ---- (D) D[m][k2] = inv * sum_k1 W[m,k1] C[k1][k2] — 2m x 4k2 ----
        if (tid < 256) {
            int mp = tid >> 3, q = tid & 7;
            int m0 = mp << 1, m1 = m0 + 1;
            int m1c = (m1 < 63) ? m1 : 62;
            int k20 = q << 2;
            const float* c0 = sct + m0*68;
            const float* s0 = sst + m0*68;
            const float* c1 = sct + m1c*68;
            const float* s1p = sst + m1c*68;
            float4 dr0={0,0,0,0}, di0={0,0,0,0}, dr1={0,0,0,0}, di1={0,0,0,0};
            #pragma unroll 7
            for (int k1 = 0; k1 < 63; k1++) {
                float cw0 = c0[k1], sw0 = s0[k1];
                float cw1 = c1[k1], sw1v = s1p[k1];
                float4 Cr = *(const float4*)(sCr + k1*36 + k20);
                float4 Ci = *(const float4*)(sCi + k1*36 + k20);
                dr0.x += cw0*Cr.x - sw0*Ci.x;  di0.x += cw0*Ci.x + sw0*Cr.x;
                dr0.y += cw0*Cr.y - sw0*Ci.y;  di0.y += cw0*Ci.y + sw0*Cr.y;
                dr0.z += cw0*Cr.z - sw0*Ci.z;  di0.z += cw0*Ci.z + sw0*Cr.z;
                dr0.w += cw0*Cr.w - sw0*Ci.w;  di0.w += cw0*Ci.w + sw0*Cr.w;
                dr1.x += cw1*Cr.x - sw1v*Ci.x;  di1.x += cw1*Ci.x + sw1v*Cr.x;
                dr1.y += cw1*Cr.y - sw1v*Ci.y;  di1.y += cw1*Ci.y + sw1v*Cr.y;
                dr1.z += cw1*Cr.z - sw1v*Ci.z;  di1.z += cw1*Ci.z + sw1v*Cr.z;
                dr1.w += cw1*Cr.w - sw1v*Ci.w;  di1.w += cw1*Ci.w + sw1v*Cr.w;
            }
            float4 R0 = {dr0.x*inv, dr0.y*inv, dr0.z*inv, dr0.w*inv};
            float4 I0 = {di0.x*inv, di0.y*inv, di0.z*inv, di0.w*inv};
            *(float4*)(sDr + m0*36 + k20) = R0;
            *(float4*)(sDi + m0*36 + k20) = I0;
            if (m1 < 63) {
                float4 R1 = {dr1.x*inv, dr1.y*inv, dr1.z*inv, dr1.w*inv};
                float4 I1 = {di1.x*inv, di1.y*inv, di1.z*inv, di1.w*inv};
                *(float4*)(sDr + m1*36 + k20) = R1;
                *(float4*)(sDi + m1*36 + k20) = I1;
            }
        }
        __syncthreads();

        // ---- (h) x[m,n] += inv*(Dr[m,0] + 2*sum Re(D[m,k2] W[k2,n])) — 2m x 4n ----
        {
            int mp = tid >> 4, g = tid & 15;
            int m0 = mp << 1, m1 = m0 + 1;
            bool two = (m1 < 63);
            int n0 = g << 2;
            const float* d0r = sDr + m0*36;
            const float* d0i = sDi + m0*36;
            const float* d1r = sDr + m1*36;
            const float* d1i = sDi + m1*36;
            float4 A0 = {0,0,0,0}, A1 = {0,0,0,0};
            float b0v = d0r[0], b1v = d1r[0];
            #pragma unroll 8
            for (int k2 = 1; k2 < 32; k2++) {
                float4 c4 = *(const float4*)(sct + k2*68 + n0);
                float4 s4 = *(const float4*)(sst + k2*68 + n0);
                float e0r = d0r[k2]*2.f, e0i = d0i[k2]*2.f;
                float e1r = d1r[k2]*2.f, e1i = d1i[k2]*2.f;
                A0.x += e0r*c4.x - e0i*s4.x;
                A0.y += e0r*c4.y - e0i*s4.y;
                A0.z += e0r*c4.z - e0i*s4.z;
                A0.w += e0r*c4.w - e0i*s4.w;
                A1.x += e1r*c4.x - e1i*s4.x;
                A1.y += e1r*c4.y - e1i*s4.y;
                A1.z += e1r*c4.z - e1i*s4.z;
                A1.w += e1r*c4.w - e1i*s4.w;
            }
            float* xo0 = sxp + (m0+1)*68 + n0 + 1;
            xo0[0] += (b0v + A0.x)*inv;
            xo0[1] += (b0v + A0.y)*inv;
            xo0[2] += (b0v + A0.z)*inv;
            if (g < 15) xo0[3] += (b0v + A0.w)*inv;
            if (two) {
                float* xo1 = sxp + (m1+1)*68 + n0 + 1;
                xo1[0] += (b1v + A1.x)*inv;
                xo1[1] += (b1v + A1.y)*inv;
                xo1[2] += (b1v + A1.z)*inv;
                if (g < 15) xo1[3] += (b1v + A1.w)*inv;
            }
        }
        __syncthreads();
    }

    // ---- final residual + sum of squares ----
    float loc = 0.f;
    #pragma unroll
    for (int p = 0; p < 8; p++) {
        int el = tid + p*T;
        if (el >= 4032) break;
        int i = el >> 6, j = el & 63;
        if (j >= 63) continue;
        const float* xb = sxp + i*68 + j;
        float acc = ska[0]*xb[0] + ska[1]*xb[1] + ska[2]*xb[2]
                  + ska[3]*xb[68] + ska[4]*xb[69] + ska[5]*xb[70]
                  + ska[6]*xb[136] + ska[7]*xb[137] + ska[8]*xb[138];
        float v = fr[p] - acc;
        loc += v * v;
    }
    #pragma unroll
    for (int off = 16; off; off >>= 1)
        loc += __shfl_xor_sync(0xFFFFFFFFu, loc, off);
    __shared__ float wsum[16];
    int wid = tid >> 5;
    if ((tid & 31) == 0) wsum[wid] = loc;
    __syncthreads();
    if (tid == 0) {
        float s = 0.f;
        #pragma unroll
        for (int w = 0; w < 16; w++) s += wsum[w];
        g_blocksum[b] = s;
    }
}

__global__ void final_reduce_kernel(float* __restrict__ out) {
    __shared__ float s[BATCH];
    s[threadIdx.x] = g_blocksum[threadIdx.x];
    __syncthreads();
    for (int st = BATCH/2; st > 0; st >>= 1) {
        if (threadIdx.x < st) s[threadIdx.x] += s[threadIdx.x + st];
        __syncthreads();
    }
    if (threadIdx.x == 0) out[0] = sqrtf(s[0]) / 256.0f;
}

// ---------------- host ----------------
extern "C" void kernel_launch(void* const* d_in, const int* in_sizes, int n_in,
                              void* d_out, int out_size) {
    const float* x      = (const float*)d_in[0];
    const float* f      = (const float*)d_in[1];
    const float* kA     = (const float*)d_in[2];
    const float* fc1_w1 = (const float*)d_in[3];
    const float* fc1_b1 = (const float*)d_in[4];
    const float* fc1_w2 = (const float*)d_in[5];
    const float* fc1_b2 = (const float*)d_in[6];
    const float* fc2_w1 = (const float*)d_in[7];
    const float* fc2_b1 = (const float*)d_in[8];
    const float* fc2_w2 = (const float*)d_in[9];
    const float* fc2_b2 = (const float*)d_in[10];
    const float* ct1_w  = (const float*)d_in[11];
    const float* ct1_b  = (const float*)d_in[12];
    const float* ct2_w  = (const float*)d_in[13];
    const float* ct2_b  = (const float*)d_in[14];
    const float* ct3_w  = (const float*)d_in[15];
    const float* ct3_b  = (const float*)d_in[16];
    const float* ct4_w  = (const float*)d_in[17];
    const float* ct4_b  = (const float*)d_in[18];
    const float* ct5_w  = (const float*)d_in[19];
    const float* ct5_b  = (const float*)d_in[20];
    float* out = (float*)d_out;

    cudaFuncSetAttribute(solver_kernel, cudaFuncAttributeMaxDynamicSharedMemorySize,
                         SMEM_FLOATS * (int)sizeof(float));
    cudaFuncSetAttribute(ctchain_kernel, cudaFuncAttributeMaxDynamicSharedMemorySize,
                         21248 * (int)sizeof(float));

    hyper_kernel<<<BATCH, 256>>>(kA, fc1_w1, fc1_b1, fc1_w2, fc1_b2,
                                 fc2_w1, fc2_b1, fc2_w2, fc2_b2);
    ctchain_kernel<<<BATCH, 512, 21248 * sizeof(float)>>>(kA, ct1_w, ct1_b, ct2_w, ct2_b,
                                                          ct3_w, ct3_b, ct4_w, ct4_b);
    init_tw_kernel<<<(63*68 + 255)/256, 256>>>();
    solver_kernel<<<BATCH, 512, SMEM_FLOATS * sizeof(float)>>>(x, f, kA, ct5_w, ct5_b);
    final_reduce_kernel<<<1, BATCH>>>(out);
}

// round 17
// speedup vs baseline: 1.1494x; 1.0039x over previous
#include <cuda_runtime.h>
#include <math.h>

#define NN 63
#define NP (NN*NN)          // 3969
#define BATCH 256
#define KS 7
#define ML 3

// ---------------- device scratch ----------------
__device__ float g_cosT[63*68];   // [k][n] rows padded to 68, cols 63..67 = 0
__device__ float g_sinT[63*68];
__device__ float g_cosTT[63*36];  // transposed [n][k2<32], stride 36
__device__ float g_sinTT[63*36];
__device__ float g_w1[BATCH*147];
__device__ float g_w2[BATCH*147];
__device__ float g_a4[BATCH*1089*32];   // [b][pix][ch]
__device__ float g_blocksum[BATCH];

__device__ __forceinline__ float gelu_exact(float v) {
    return v * 0.5f * (1.0f + erff(v * 0.70710678118654752f));
}

__global__ void init_tw_kernel() {
    int idx = blockIdx.x * blockDim.x + threadIdx.x;
    if (idx < 63*68) {
        int k = idx / 68, n = idx % 68;
        if (n < 63) {
            float ang = 6.28318530717958647692f * (float)((k * n) % NN) / 63.0f;
            g_cosT[idx] = cosf(ang);
            g_sinT[idx] = sinf(ang);
        } else { g_cosT[idx] = 0.f; g_sinT[idx] = 0.f; }
    }
    if (idx < 63*36) {
        int n = idx / 36, k2 = idx % 36;
        if (k2 < 32) {
            float ang = 6.28318530717958647692f * (float)((k2 * n) % NN) / 63.0f;
            g_cosTT[idx] = cosf(ang);
            g_sinTT[idx] = sinf(ang);
        } else { g_cosTT[idx] = 0.f; g_sinTT[idx] = 0.f; }
    }
}

// ---------------- fused ConvTranspose chain ct1..ct4 + hypernet ----------------
__device__ __forceinline__ void load_ctw(const float* __restrict__ w,
                                         const float* __restrict__ bias,
                                         float* s_w, float* s_bias, int tid) {
    for (int idx = tid; idx < 9216; idx += 512) {
        int i = idx & 31, o = (idx >> 5) & 31, k = idx >> 10;
        s_w[k*1040 + (o>>3)*260 + (o&7)*32 + i] = w[(i*32 + o)*9 + k];
    }
    if (tid < 32) s_bias[tid] = bias[tid];
}

__device__ __forceinline__ void ct_store(float* __restrict__ ob, const float* acc) {
    float4 o0 = {gelu_exact(acc[0]), gelu_exact(acc[1]), gelu_exact(acc[2]), gelu_exact(acc[3])};
    float4 o1 = {gelu_exact(acc[4]), gelu_exact(acc[5]), gelu_exact(acc[6]), gelu_exact(acc[7])};
    *(float4*)ob = o0;
    *(float4*)(ob + 4) = o1;
}

// PIXEL-PAIR blocking: each thread computes (y,x) and (y,x+2)
// (same parity class -> identical tap list & weight addresses -> weight loads
//  amortized over 2 outputs). Singleton pairs (even-series tail) predicate off
//  the second store; their extra loads stay inside block smem (dead buffer).
template<int IN_H>
__device__ void ct_midstage(const float* __restrict__ s_in, const float* __restrict__ s_w,
                            const float* __restrict__ s_bias, float* __restrict__ out, int tid) {
    constexpr int OUT_H = 2*IN_H - 1;
    constexpr int EC = (OUT_H + 1) / 2;       // even-column count
    constexpr int OC = OUT_H - EC;            // odd-column count
    constexpr int PE = (EC + 1) / 2;          // even-series pairs (last is singleton)
    constexpr int PO = (OC + 1) / 2;          // odd-series pairs (always full here)
    constexpr int PPR = PE + PO;              // pairs per row
    constexpr int ITEMS = OUT_H * PPR * 4;
    const float4* in4 = (const float4*)s_in;
    const float4* w4  = (const float4*)s_w;
    for (int it = tid; it < ITEMS; it += 512) {
        int og = it & 3, t = it >> 2;
        int y = t / PPR, pr = t % PPR;
        int x; bool valid2;
        if (pr < PE) { x = 4*pr;            valid2 = (x + 2) < OUT_H; }
        else         { x = 1 + 4*(pr - PE); valid2 = true; }
        float accA[8], accB[8];
        #pragma unroll
        for (int ol = 0; ol < 8; ol++) { accA[ol] = s_bias[og*8 + ol]; accB[ol] = accA[ol]; }
        int kys[2], iys[2], nky, kxs[2], ixs[2], nkx;
        if (y & 1) { nky=2; kys[0]=0; iys[0]=(y+1)>>1; kys[1]=2; iys[1]=(y-1)>>1; }
        else       { nky=1; kys[0]=1; iys[0]=y>>1; }
        if (x & 1) { nkx=2; kxs[0]=0; ixs[0]=(x+1)>>1; kxs[1]=2; ixs[1]=(x-1)>>1; }
        else       { nkx=1; kxs[0]=1; ixs[0]=x>>1; }
        for (int p = 0; p < nky; p++)
            for (int q = 0; q < nkx; q++) {
                int base4 = (iys[p]*IN_H + ixs[q]) * 8;
                const float4* wrow = w4 + (kys[p]*3 + kxs[q])*260 + og*65;
                #pragma unroll
                for (int c4 = 0; c4 < 8; c4++) {
                    float4 va = in4[base4 + c4];
                    float4 vb = in4[base4 + 8 + c4];   // second pixel: ix+1
                    #pragma unroll
                    for (int ol = 0; ol < 8; ol++) {
                        float4 wv = wrow[ol*8 + c4];
                        accA[ol] += va.x*wv.x + va.y*wv.y + va.z*wv.z + va.w*wv.w;
                        accB[ol] += vb.x*wv.x + vb.y*wv.y + vb.z*wv.z + vb.w*wv.w;
                    }
                }
            }
        int pixA = y*OUT_H + x;
        ct_store(out + pixA*32 + og*8, accA);
        if (valid2) ct_store(out + (pixA + 2)*32 + og*8, accB);
    }
}

__global__ void __launch_bounds__(512) ctchain_kernel(
    const float* __restrict__ kA,
    const float* __restrict__ w1c, const float* __restrict__ b1c,
    const float* __restrict__ w2c, const float* __restrict__ b2c,
    const float* __restrict__ w3c, const float* __restrict__ b3c,
    const float* __restrict__ w4c, const float* __restrict__ b4c,
    const float* __restrict__ w1a, const float* __restrict__ b1a,
    const float* __restrict__ w2a, const float* __restrict__ b2a,
    const float* __restrict__ w1b, const float* __restrict__ b1b,
    const float* __restrict__ w2b, const float* __restrict__ b2b) {
    extern __shared__ float cs[];
    float* s_w    = cs;               // 9360
    float* B1     = cs + 9360;        // 9248
    float* B2     = B1 + 9248;        // 2592
    float* s_a    = B2 + 2592;        // 16
    float* s_bias = s_a + 16;         // 32
    int b = blockIdx.x, tid = threadIdx.x;

    if (tid < 9) s_a[tid] = kA[b*9 + tid];
    load_ctw(w2c, b2c, s_w, s_bias, tid);
    __syncthreads();

    // ---- fused hypernet (h1/h2 staged in B2, dead until midstage<5>) ----
    if (tid < 100) {
        float s = b1a[tid];
        #pragma unroll
        for (int i = 0; i < 9; i++) s += s_a[i] * w1a[i*100 + tid];
        B2[tid] = gelu_exact(s);
    } else if (tid < 200) {
        int h = tid - 100;
        float s = b1b[h];
        #pragma unroll
        for (int i = 0; i < 9; i++) s += s_a[i] * w1b[i*100 + h];
        B2[100 + h] = gelu_exact(s);
    }
    __syncthreads();
    for (int o = tid; o < 147; o += 512) {
        float s1 = b2a[o], s2 = b2b[o];
        for (int h = 0; h < 100; h++) {
            s1 += B2[h] * w2a[h*147 + o];
            s2 += B2[100 + h] * w2b[h*147 + o];
        }
        g_w1[b*147 + o] = s1;
        g_w2[b*147 + o] = s2;
    }

    // ---- ct1 (no sync needed before: writes B1, reads s_a/w1c only) ----
    for (int el = tid; el < 800; el += 512) {
        int pix = el >> 5, o = el & 31;
        int y = pix / 5, x = pix % 5;
        float acc = b1c[o];
        int kys[2], iys[2], nky, kxs[2], ixs[2], nkx;
        if (y & 1) { nky=2; kys[0]=0; iys[0]=(y+1)>>1; kys[1]=2; iys[1]=(y-1)>>1; }
        else       { nky=1; kys[0]=1; iys[0]=y>>1; }
        if (x & 1) { nkx=2; kxs[0]=0; ixs[0]=(x+1)>>1; kxs[1]=2; ixs[1]=(x-1)>>1; }
        else       { nkx=1; kxs[0]=1; ixs[0]=x>>1; }
        for (int p = 0; p < nky; p++)
            for (int q = 0; q < nkx; q++)
                acc += s_a[iys[p]*3 + ixs[q]] * w1c[o*9 + kys[p]*3 + kxs[q]];
        B1[pix*32 + o] = gelu_exact(acc);
    }
    __syncthreads();   // orders B1 writes AND B2 hypernet reads before midstage<5> writes B2

    ct_midstage<5>(B1, s_w, s_bias, B2, tid);
    __syncthreads();
    load_ctw(w3c, b3c, s_w, s_bias, tid);
    __syncthreads();
    ct_midstage<9>(B2, s_w, s_bias, B1, tid);
    __syncthreads();
    load_ctw(w4c, b4c, s_w, s_bias, tid);
    __syncthreads();
    ct_midstage<17>(B1, s_w, s_bias, g_a4 + (size_t)b*1089*32, tid);
}

// ---------------- persistent per-sample solver (R8/R12 verbatim) ----------------
#define O_SXP 0                      // 65x68 = 4420
#define O_SRP 4420                   // 69x72 = 4968
#define O_T   9388                   // 3*4968 = 14904 (ct5 staging 7938 fits)
#define O_PR  24292                  // [m][36] = 2268
#define O_PI  26560
#define O_CR  28828                  // [k1][36] = 2268
#define O_CI  31096
#define O_DR  33364                  // [m][36] = 2268
#define O_DI  35632
#define O_WCR 37900                  // [k1][36] = 2268
#define O_WCI 40168
#define O_CT  42436                  // [k][68] = 4284
#define O_ST  46720
#define O_TTC 51004                  // [n][36] = 2268
#define O_TTS 53272
#define O_W5  55540                  // 576
#define O_W1  56116                  // 160
#define O_W2  56276
#define O_KA  56436
#define SMEM_FLOATS 56452            // 225808 B

__global__ void __launch_bounds__(512) solver_kernel(const float* __restrict__ x_in,
                              const float* __restrict__ f_in,
                              const float* __restrict__ kA,
                              const float* __restrict__ w5, const float* __restrict__ b5) {
    extern __shared__ float sm[];
    float* sxp  = sm + O_SXP;
    float* srp  = sm + O_SRP;
    float* sT   = sm + O_T;
    float* sPr  = sm + O_PR;
    float* sPi  = sm + O_PI;
    float* sCr  = sm + O_CR;
    float* sCi  = sm + O_CI;
    float* sDr  = sm + O_DR;
    float* sDi  = sm + O_DI;
    float* swcr = sm + O_WCR;
    float* swci = sm + O_WCI;
    float* sct  = sm + O_CT;
    float* sst  = sm + O_ST;
    float* sttc = sm + O_TTC;
    float* stts = sm + O_TTS;
    float* sw5  = sm + O_W5;
    float* sw1  = sm + O_W1;
    float* sw2  = sm + O_W2;
    float* ska  = sm + O_KA;

    int b = blockIdx.x, tid = threadIdx.x;
    const int T = 512;
    const float inv = 0.12598815766974242f;  // 1/sqrt(63)

    // ---- init ----
    float fr[8];
    #pragma unroll
    for (int p = 0; p < 8; p++) {
        int el = tid + p*T;
        fr[p] = 0.f;
        if (el < 4032) {
            int i = el >> 6, j = el & 63;
            if (j < 63) {
                fr[p] = f_in[b*NP + i*NN + j];
                sxp[(i+1)*68 + (j+1)] = x_in[b*NP + i*NN + j];
            }
        }
    }
    for (int el = tid; el < 63*68; el += T) { sct[el] = g_cosT[el]; sst[el] = g_sinT[el]; }
    for (int el = tid; el < 63*36; el += T) { sttc[el] = g_cosTT[el]; stts[el] = g_sinTT[el]; }
    for (int c = tid; c < 65; c += T) {
        sxp[c] = (c == 64) ? 1.f : 0.f;
        sxp[64*68 + c] = 1.f;
    }
    for (int r = tid; r < 65; r += T) {
        sxp[r*68] = (r == 64) ? 1.f : 0.f;
        sxp[r*68 + 64] = 1.f;
    }
    for (int idx = tid; idx < 576; idx += T) {
        int k = idx / 64, r = idx & 63, o = r >> 5, i = r & 31;
        sw5[idx] = w5[i*18 + o*9 + k];
    }
    if (tid < 9) ska[tid] = kA[b*9 + tid];
    for (int el = tid; el < 147; el += T) {
        sw1[el] = g_w1[b*147 + el];
        sw2[el] = g_w2[b*147 + el];
    }
    __syncthreads();

    // ---- ct5 fused: h flat [2][63*63] into sT staging ----
    {
        float b0 = b5[0], b1 = b5[1];
        const float4* s_w4 = (const float4*)sw5;
        const float4* gin = (const float4*)(g_a4 + (size_t)b * 1089 * 32);
        for (int pix = tid; pix < NP; pix += T) {
            int y = pix / NN, x = pix % NN;
            float acc0 = b0, acc1 = b1;
            int kys[2], iys[2], nky, kxs[2], ixs[2], nkx;
            if (y & 1) { nky=1; kys[0]=1; iys[0]=(y+1)>>1; }
            else       { nky=2; kys[0]=0; iys[0]=(y+2)>>1; kys[1]=2; iys[1]=y>>1; }
            if (x & 1) { nkx=1; kxs[0]=1; ixs[0]=(x+1)>>1; }
            else       { nkx=2; kxs[0]=0; ixs[0]=(x+2)>>1; kxs[1]=2; ixs[1]=x>>1; }
            for (int p = 0; p < nky; p++)
                for (int q = 0; q < nkx; q++) {
                    int base4 = (iys[p]*33 + ixs[q]) * 8;
                    int kk = kys[p]*3 + kxs[q];
                    #pragma unroll
                    for (int c4 = 0; c4 < 8; c4++) {
                        float4 v = __ldg(gin + base4 + c4);
                        float4 w0 = s_w4[kk*16 + c4];
                        float4 w1 = s_w4[kk*16 + 8 + c4];
                        acc0 += v.x*w0.x + v.y*w0.y + v.z*w0.z + v.w*w0.w;
                        acc1 += v.x*w1.x + v.y*w1.y + v.z*w1.z + v.w*w1.w;
                    }
                }
            sT[pix] = acc0;
            sT[NP + pix] = acc1;
        }
    }
    __syncthreads();
    for (int el = tid; el < 2016; el += T) {
        int k1 = el >> 5, k2 = el & 31;
        int p = k1*63 + k2;
        swcr[k1*36 + k2] = sT[2*p];
        swci[k1*36 + k2] = sT[2*p + 1];
    }
    __syncthreads();
    for (int el = tid; el < 14904; el += T) sT[el] = 0.f;
    for (int el = tid; el < 4968; el += T) srp[el] = 0.f;
    __syncthreads();

    for (int iter = 0; iter < 5; iter++) {
        // ---- (a) residual -> srp ----
        #pragma unroll
        for (int p = 0; p < 8; p++) {
            int el = tid + p*T;
            if (el >= 4032) break;
            int i = el >> 6, j = el & 63;
            if (j >= 63) continue;
            const float* xb = sxp + i*68 + j;
            float acc = ska[0]*xb[0] + ska[1]*xb[1] + ska[2]*xb[2]
                      + ska[3]*xb[68] + ska[4]*xb[69] + ska[5]*xb[70]
                      + ska[6]*xb[136] + ska[7]*xb[137] + ska[8]*xb[138];
            srp[(i+3)*72 + j + 4] = fr[p] - acc;
        }
        __syncthreads();

        // ---- (b) stage1: t[c] = conv7(r, w1[c]) — 2-row blocked, 3 channels ----
        {
            int rpair = tid >> 4, g = tid & 15;
            int i0 = rpair << 1;
            bool two = (i0 + 1 < 63);
            int j0 = g << 2;
            float4 a00={0,0,0,0}, a01={0,0,0,0}, a02={0,0,0,0};
            float4 a10={0,0,0,0}, a11={0,0,0,0}, a12={0,0,0,0};
            #pragma unroll
            for (int rr_ = 0; rr_ < 8; rr_++) {
                if (rr_ == 7 && !two) break;
                const float4* rp4 = (const float4*)(srp + (i0+rr_)*72 + j0);
                float4 Ra = rp4[0], Rb = rp4[1], Rc = rp4[2];
                float rr[12] = {Ra.x,Ra.y,Ra.z,Ra.w, Rb.x,Rb.y,Rb.z,Rb.w, Rc.x,Rc.y,Rc.z,Rc.w};
                if (rr_ < 7) {
                    #pragma unroll
                    for (int v = 0; v < 7; v++) {
                        float w0 = sw1[rr_*7 + v];
                        float w1 = sw1[49 + rr_*7 + v];
                        float w2 = sw1[98 + rr_*7 + v];
                        a00.x += rr[v+1]*w0; a00.y += rr[v+2]*w0; a00.z += rr[v+3]*w0; a00.w += rr[v+4]*w0;
                        a01.x += rr[v+1]*w1; a01.y += rr[v+2]*w1; a01.z += rr[v+3]*w1; a01.w += rr[v+4]*w1;
                        a02.x += rr[v+1]*w2; a02.y += rr[v+2]*w2; a02.z += rr[v+3]*w2; a02.w += rr[v+4]*w2;
                    }
                }
                if (rr_ >= 1) {
                    int u = rr_ - 1;
                    #pragma unroll
                    for (int v = 0; v < 7; v++) {
                        float w0 = sw1[u*7 + v];
                        float w1 = sw1[49 + u*7 + v];
                        float w2 = sw1[98 + u*7 + v];
                        a10.x += rr[v+1]*w0; a10.y += rr[v+2]*w0; a10.z += rr[v+3]*w0; a10.w += rr[v+4]*w0;
                        a11.x += rr[v+1]*w1; a11.y += rr[v+2]*w1; a11.z += rr[v+3]*w1; a11.w += rr[v+4]*w1;
                        a12.x += rr[v+1]*w2; a12.y += rr[v+2]*w2; a12.z += rr[v+3]*w2; a12.w += rr[v+4]*w2;
                    }
                }
            }
            float* o0 = sT + (i0+3)*72 + j0 + 4;
            if (g < 15) {
                *(float4*)o0 = a00; *(float4*)(o0+4968) = a01; *(float4*)(o0+9936) = a02;
                if (two) {
                    float* o1 = o0 + 72;
                    *(float4*)o1 = a10; *(float4*)(o1+4968) = a11; *(float4*)(o1+9936) = a12;
                }
            } else {
                o0[0]=a00.x; o0[1]=a00.y; o0[2]=a00.z;
                o0[4968]=a01.x; o0[4969]=a01.y; o0[4970]=a01.z;
                o0[9936]=a02.x; o0[9937]=a02.y; o0[9938]=a02.z;
                if (two) {
                    float* o1 = o0 + 72;
                    o1[0]=a10.x; o1[1]=a10.y; o1[2]=a10.z;
                    o1[4968]=a11.x; o1[4969]=a11.y; o1[4970]=a11.z;
                    o1[9936]=a12.x; o1[9937]=a12.y; o1[9938]=a12.z;
                }
            }
        }
        __syncthreads();

        // ---- (c) stage2: x += sum_c conv7(t[c], w2[c]) — 2-row x 8-wide ----
        if (tid < 256) {
            int rp = tid >> 3, g = tid & 7;
            int i0 = rp << 1;
            bool two = (i0 + 1 < 63);
            int j0 = g << 3;
            float4 A0a={0,0,0,0}, A0b={0,0,0,0}, A1a={0,0,0,0}, A1b={0,0,0,0};
            #pragma unroll
            for (int c = 0; c < 3; c++) {
                const float* tb = sT + c*4968;
                const float* wc_ = sw2 + c*49;
                #pragma unroll
                for (int rr_ = 0; rr_ < 8; rr_++) {
                    if (rr_ == 7 && !two) break;
                    const float4* rp4 = (const float4*)(tb + (i0+rr_)*72 + j0);
                    float4 Ra = rp4[0], Rb = rp4[1], Rc = rp4[2], Rd = rp4[3];
                    float rr[16] = {Ra.x,Ra.y,Ra.z,Ra.w, Rb.x,Rb.y,Rb.z,Rb.w,
                                    Rc.x,Rc.y,Rc.z,Rc.w, Rd.x,Rd.y,Rd.z,Rd.w};
                    if (rr_ < 7) {
                        #pragma unroll
                        for (int v = 0; v < 7; v++) {
                            float wv = wc_[rr_*7 + v];
                            A0a.x += rr[v+1]*wv; A0a.y += rr[v+2]*wv;
                            A0a.z += rr[v+3]*wv; A0a.w += rr[v+4]*wv;
                            A0b.x += rr[v+5]*wv; A0b.y += rr[v+6]*wv;
                            A0b.z += rr[v+7]*wv; A0b.w += rr[v+8]*wv;
                        }
                    }
                    if (rr_ >= 1) {
                        int u = rr_ - 1;
                        #pragma unroll
                        for (int v = 0; v < 7; v++) {
                            float wv = wc_[u*7 + v];
                            A1a.x += rr[v+1]*wv; A1a.y += rr[v+2]*wv;
                            A1a.z += rr[v+3]*wv; A1a.w += rr[v+4]*wv;
                            A1b.x += rr[v+5]*wv; A1b.y += rr[v+6]*wv;
                            A1b.z += rr[v+7]*wv; A1b.w += rr[v+8]*wv;
                        }
                    }
                }
            }
            float* xo0 = sxp + (i0+1)*68 + j0 + 1;
            xo0[0]+=A0a.x; xo0[1]+=A0a.y; xo0[2]+=A0a.z; xo0[3]+=A0a.w;
            xo0[4]+=A0b.x; xo0[5]+=A0b.y; xo0[6]+=A0b.z;
            if (g < 7) xo0[7]+=A0b.w;
            if (two) {
                float* xo1 = xo0 + 68;
                xo1[0]+=A1a.x; xo1[1]+=A1a.y; xo1[2]+=A1a.z; xo1[3]+=A1a.w;
                xo1[4]+=A1b.x; xo1[5]+=A1b.y; xo1[6]+=A1b.z;
                if (g < 7) xo1[7]+=A1b.w;
            }
        }
        __syncthreads();

        // ---- (d) residual -> srp ----
        #pragma unroll
        for (int p = 0; p < 8; p++) {
            int el = tid + p*T;
            if (el >= 4032) break;
            int i = el >> 6, j = el & 63;
            if (j >= 63) continue;
            const float* xb = sxp + i*68 + j;
            float acc = ska[0]*xb[0] + ska[1]*xb[1] + ska[2]*xb[2]
                      + ska[3]*xb[68] + ska[4]*xb[69] + ska[5]*xb[70]
                      + ska[6]*xb[136] + ska[7]*xb[137] + ska[8]*xb[138];
            srp[(i+3)*72 + j + 4] = fr[p] - acc;
        }
        __syncthreads();

        // ---- (P) P[m][k2] = inv * sum_n r[m,n] conj(W[k2,n]) — 2m x 4k2 ----
        if (tid < 256) {
            int mp = tid >> 3, q = tid & 7;
            int m0 = mp << 1, m1 = m0 + 1;
            int k20 = q << 2;
            const float* r0p = srp + (m0+3)*72 + 4;
            const float* r1p = r0p + 72;
            float4 ar0={0,0,0,0}, ai0={0,0,0,0}, ar1={0,0,0,0}, ai1={0,0,0,0};
            #pragma unroll 7
            for (int n = 0; n < 63; n++) {
                float rv0 = r0p[n], rv1 = r1p[n];
                float4 c = *(const float4*)(sttc + n*36 + k20);
                float4 s = *(const float4*)(stts + n*36 + k20);
                ar0.x += rv0*c.x; ar0.y += rv0*c.y; ar0.z += rv0*c.z; ar0.w += rv0*c.w;
                ai0.x -= rv0*s.x; ai0.y -= rv0*s.y; ai0.z -= rv0*s.z; ai0.w -= rv0*s.w;
                ar1.x += rv1*c.x; ar1.y += rv1*c.y; ar1.z += rv1*c.z; ar1.w += rv1*c.w;
                ai1.x -= rv1*s.x; ai1.y -= rv1*s.y; ai1.z -= rv1*s.z; ai1.w -= rv1*s.w;
            }
            float4 R0 = {ar0.x*inv, ar0.y*inv, ar0.z*inv, ar0.w*inv};
            float4 I0 = {ai0.x*inv, ai0.y*inv, ai0.z*inv, ai0.w*inv};
            *(float4*)(sPr + m0*36 + k20) = R0;
            *(float4*)(sPi + m0*36 + k20) = I0;
            if (m1 < 63) {
                float4 R1 = {ar1.x*inv, ar1.y*inv, ar1.z*inv, ar1.w*inv};
                float4 I1 = {ai1.x*inv, ai1.y*inv, ai1.z*inv, ai1.w*inv};
                *(float4*)(sPr + m1*36 + k20) = R1;
                *(float4*)(sPi + m1*36 + k20) = I1;
            }
        }
        __syncthreads();

        // ---- (C) C[k1][k2] = (inv * sum_m conj(W[k1,m]) P[m][k2]) * wc — 2k1 x 4k2 ----
        if (tid < 256) {
            int kp = tid >> 3, q = tid & 7;
            int k10 = kp << 1, k11 = k10 + 1;
            int k11c = (k11 < 63) ? k11 : 62;
            int k20 = q << 2;
            const float* c0 = sct + k10*68;
            const float* s0 = sst + k10*68;
            const float* c1 = sct + k11c*68;
            const float* s1p = sst + k11c*68;
            float4 ar0={0,0,0,0}, ai0={0,0,0,0}, ar1={0,0,0,0}, ai1={0,0,0,0};
            #pragma unroll 7
            for (int m = 0; m < 63; m++) {
                float cw0 = c0[m], sw0 = s0[m];
                float cw1 = c1[m], sw1v = s1p[m];
                float4 pr = *(const float4*)(sPr + m*36 + k20);
                float4 pi = *(const float4*)(sPi + m*36 + k20);
                ar0.x += cw0*pr.x + sw0*pi.x;  ai0.x += cw0*pi.x - sw0*pr.x;
                ar0.y += cw0*pr.y + sw0*pi.y;  ai0.y += cw0*pi.y - sw0*pr.y;
                ar0.z += cw0*pr.z + sw0*pi.z;  ai0.z += cw0*pi.z - sw0*pr.z;
                ar0.w += cw0*pr.w + sw0*pi.w;  ai0.w += cw0*pi.w - sw0*pr.w;
                ar1.x += cw1*pr.x + sw1v*pi.x;  ai1.x += cw1*pi.x - sw1v*pr.x;
                ar1.y += cw1*pr.y + sw1v*pi.y;  ai1.y += cw1*pi.y - sw1v*pr.y;
                ar1.z += cw1*pr.z + sw1v*pi.z;  ai1.z += cw1*pi.z - sw1v*pr.z;
                ar1.w += cw1*pr.w + sw1v*pi.w;  ai1.w += cw1*pi.w - sw1v*pr.w;
            }
            {
                float4 wr = *(const float4*)(swcr + k10*36 + k20);
                float4 wi = *(const float4*)(swci + k10*36 + k20);
                float4 arv = {ar0.x*inv, ar0.y*inv, ar0.z*inv, ar0.w*inv};
                float4 aiv = {ai0.x*inv, ai0.y*inv, ai0.z*inv, ai0.w*inv};
                float4 cr = {arv.x*wr.x - aiv.x*wi.x, arv.y*wr.y - aiv.y*wi.y,
                             arv.z*wr.z - aiv.z*wi.z, arv.w*wr.w - aiv.w*wi.w};
                float4 ci = {arv.x*wi.x + aiv.x*wr.x, arv.y*wi.y + aiv.y*wr.y,
                             arv.z*wi.z + aiv.z*wr.z, arv.w*wi.w + aiv.w*wr.w};
                *(float4*)(sCr + k10*36 + k20) = cr;
                *(float4*)(sCi + k10*36 + k20) = ci;
            }
            if (k11 < 63) {
                float4 wr = *(const float4*)(swcr + k11*36 + k20);
                float4 wi = *(const float4*)(swci + k11*36 + k20);
                float4 arv = {ar1.x*inv, ar1.y*inv, ar1.z*inv, ar1.w*inv};
                float4 aiv = {ai1.x*inv, ai1.y*inv, ai1.z*inv, ai1.w*inv};
                float4 cr = {arv.x*wr.x - aiv.x*wi.x, arv.y*wr.y - aiv.y*wi.y,
                             arv.z*wr.z - aiv.z*wi.z, arv.w*wr.w - aiv.w*wi.w};
                float4 ci = {arv.x*wi.x + aiv.x*wr.x, arv.y*wi.y + aiv.y*wr.y,
                             arv.z*wi.z + aiv.z*wr.z, arv.w*wi.w + aiv.w*wr.w};
                *(float4*)(sCr + k11*36 + k20) = cr;
                *(float4*)(sCi + k11*36 + k20) = ci;
            }
        }
        __syncthreads();

        // ---- (D) D[m][k2] = inv * sum_k1 W[m,k1] C[k1][k2] — 2m x 4k2 ----
        if (tid < 256) {
            int mp = tid >> 3, q = tid & 7;
            int m0 = mp << 1, m1 = m0 + 1;
            int m1c = (m1 < 63) ? m1 : 62;
            int k20 = q << 2;
            const float* c0 = sct + m0*68;
            const float* s0 = sst + m0*68;
            const float* c1 = sct + m1c*68;
            const float* s1p = sst + m1c*68;
            float4 dr0={0,0,0,0}, di0={0,0,0,0}, dr1={0,0,0,0}, di1={0,0,0,0};
            #pragma unroll 7
            for (int k1 = 0; k1 < 63; k1++) {
                float cw0 = c0[k1], sw0 = s0[k1];
                float cw1 = c1[k1], sw1v = s1p[k1];
                float4 Cr = *(const float4*)(sCr + k1*36 + k20);
                float4 Ci = *(const float4*)(sCi + k1*36 + k20);
                dr0.x += cw0*Cr.x - sw0*Ci.x;  di0.x += cw0*Ci.x + sw0*Cr.x;
                dr0.y += cw0*Cr.y - sw0*Ci.y;  di0.y += cw0*Ci.y + sw0*Cr.y;
                dr0.z += cw0*Cr.z - sw0*Ci.z;  di0.z += cw0*Ci.z + sw0*Cr.z;
                dr0.w += cw0*Cr.w - sw0*Ci.w;  di0.w += cw0*Ci.w + sw0*Cr.w;
                dr1.x += cw1*Cr.x - sw1v*Ci.x;  di1.x += cw1*Ci.x + sw1v*Cr.x;
                dr1.y += cw1*Cr.y - sw1v*Ci.y;  di1.y += cw1*Ci.y + sw1v*Cr.y;
                dr1.z += cw1*Cr.z - sw1v*Ci.z;  di1.z += cw1*Ci.z + sw1v*Cr.z;
                dr1.w += cw1*Cr.w - sw1v*Ci.w;  di1.w += cw1*Ci.w + sw1v*Cr.w;
            }
            float4 R0 = {dr0.x*inv, dr0.y*inv, dr0.z*inv, dr0.w*inv};
            float4 I0 = {di0.x*inv, di0.y*inv, di0.z*inv, di0.w*inv};
            *(float4*)(sDr + m0*36 + k20) = R0;
            *(float4*)(sDi + m0*36 + k20) = I0;
            if (m1 < 63) {
                float4 R1 = {dr1.x*inv, dr1.y*inv, dr1.z*inv, dr1.w*inv};
                float4 I1 = {di1.x*inv, di1.y*inv, di1.z*inv, di1.w*inv};
                *(float4*)(sDr + m1*36 + k20) = R1;
                *(float4*)(sDi + m1*36 + k20) = I1;
            }
        }
        __syncthreads();

        // ---- (h) x[m,n] += inv*(Dr[m,0] + 2*sum Re(D[m,k2] W[k2,n])) — 2m x 4n ----
        {
            int mp = tid >> 4, g = tid & 15;
            int m0 = mp << 1, m1 = m0 + 1;
            bool two = (m1 < 63);
            int n0 = g << 2;
            const float* d0r = sDr + m0*36;
            const float* d0i = sDi + m0*36;
            const float* d1r = sDr + m1*36;
            const float* d1i = sDi + m1*36;
            float4 A0 = {0,0,0,0}, A1 = {0,0,0,0};
            float b0v = d0r[0], b1v = d1r[0];
            #pragma unroll 8
            for (int k2 = 1; k2 < 32; k2++) {
                float4 c4 = *(const float4*)(sct + k2*68 + n0);
                float4 s4 = *(const float4*)(sst + k2*68 + n0);
                float e0r = d0r[k2]*2.f, e0i = d0i[k2]*2.f;
                float e1r = d1r[k2]*2.f, e1i = d1i[k2]*2.f;
                A0.x += e0r*c4.x - e0i*s4.x;
                A0.y += e0r*c4.y - e0i*s4.y;
                A0.z += e0r*c4.z - e0i*s4.z;
                A0.w += e0r*c4.w - e0i*s4.w;
                A1.x += e1r*c4.x - e1i*s4.x;
                A1.y += e1r*c4.y - e1i*s4.y;
                A1.z += e1r*c4.z - e1i*s4.z;
                A1.w += e1r*c4.w - e1i*s4.w;
            }
            float* xo0 = sxp + (m0+1)*68 + n0 + 1;
            xo0[0] += (b0v + A0.x)*inv;
            xo0[1] += (b0v + A0.y)*inv;
            xo0[2] += (b0v + A0.z)*inv;
            if (g < 15) xo0[3] += (b0v + A0.w)*inv;
            if (two) {
                float* xo1 = sxp + (m1+1)*68 + n0 + 1;
                xo1[0] += (b1v + A1.x)*inv;
                xo1[1] += (b1v + A1.y)*inv;
                xo1[2] += (b1v + A1.z)*inv;
                if (g < 15) xo1[3] += (b1v + A1.w)*inv;
            }
        }
        __syncthreads();
    }

    // ---- final residual + sum of squares ----
    float loc = 0.f;
    #pragma unroll
    for (int p = 0; p < 8; p++) {
        int el = tid + p*T;
        if (el >= 4032) break;
        int i = el >> 6, j = el & 63;
        if (j >= 63) continue;
        const float* xb = sxp + i*68 + j;
        float acc = ska[0]*xb[0] + ska[1]*xb[1] + ska[2]*xb[2]
                  + ska[3]*xb[68] + ska[4]*xb[69] + ska[5]*xb[70]
                  + ska[6]*xb[136] + ska[7]*xb[137] + ska[8]*xb[138];
        float v = fr[p] - acc;
        loc += v * v;
    }
    #pragma unroll
    for (int off = 16; off; off >>= 1)
        loc += __shfl_xor_sync(0xFFFFFFFFu, loc, off);
    __shared__ float wsum[16];
    int wid = tid >> 5;
    if ((tid & 31) == 0) wsum[wid] = loc;
    __syncthreads();
    if (tid == 0) {
        float s = 0.f;
        #pragma unroll
        for (int w = 0; w < 16; w++) s += wsum[w];
        g_blocksum[b] = s;
    }
}

__global__ void final_reduce_kernel(float* __restrict__ out) {
    __shared__ float s[BATCH];
    s[threadIdx.x] = g_blocksum[threadIdx.x];
    __syncthreads();
    for (int st = BATCH/2; st > 0; st >>= 1) {
        if (threadIdx.x < st) s[threadIdx.x] += s[threadIdx.x + st];
        __syncthreads();
    }
    if (threadIdx.x == 0) out[0] = sqrtf(s[0]) / 256.0f;
}

// ---------------- host ----------------
extern "C" void kernel_launch(void* const* d_in, const int* in_sizes, int n_in,
                              void* d_out, int out_size) {
    const float* x      = (const float*)d_in[0];
    const float* f      = (const float*)d_in[1];
    const float* kA     = (const float*)d_in[2];
    const float* fc1_w1 = (const float*)d_in[3];
    const float* fc1_b1 = (const float*)d_in[4];
    const float* fc1_w2 = (const float*)d_in[5];
    const float* fc1_b2 = (const float*)d_in[6];
    const float* fc2_w1 = (const float*)d_in[7];
    const float* fc2_b1 = (const float*)d_in[8];
    const float* fc2_w2 = (const float*)d_in[9];
    const float* fc2_b2 = (const float*)d_in[10];
    const float* ct1_w  = (const float*)d_in[11];
    const float* ct1_b  = (const float*)d_in[12];
    const float* ct2_w  = (const float*)d_in[13];
    const float* ct2_b  = (const float*)d_in[14];
    const float* ct3_w  = (const float*)d_in[15];
    const float* ct3_b  = (const float*)d_in[16];
    const float* ct4_w  = (const float*)d_in[17];
    const float* ct4_b  = (const float*)d_in[18];
    const float* ct5_w  = (const float*)d_in[19];
    const float* ct5_b  = (const float*)d_in[20];
    float* out = (float*)d_out;

    cudaFuncSetAttribute(solver_kernel, cudaFuncAttributeMaxDynamicSharedMemorySize,
                         SMEM_FLOATS * (int)sizeof(float));
    cudaFuncSetAttribute(ctchain_kernel, cudaFuncAttributeMaxDynamicSharedMemorySize,
                         21248 * (int)sizeof(float));

    ctchain_kernel<<<BATCH, 512, 21248 * sizeof(float)>>>(kA, ct1_w, ct1_b, ct2_w, ct2_b,
                                                          ct3_w, ct3_b, ct4_w, ct4_b,
                                                          fc1_w1, fc1_b1, fc1_w2, fc1_b2,
                                                          fc2_w1, fc2_b1, fc2_w2, fc2_b2);
    init_tw_kernel<<<(63*68 + 255)/256, 256>>>();
    solver_kernel<<<BATCH, 512, SMEM_FLOATS * sizeof(float)>>>(x, f, kA, ct5_w, ct5_b);
    final_reduce_kernel<<<1, BATCH>>>(out);
}